// round 3
// baseline (speedup 1.0000x reference)
#include <cuda_runtime.h>
#include <math.h>

// Problem constants
#define NB     2048            // batch (episodes)
#define NN     26              // nodes per episode
#define FD     1024            // feature dim
#define HD     512             // hidden dim
#define E6     6               // distinct rows per episode (5 class means + query)
#define ET     (NB * E6)       // 12288 effective GEMM rows

// ---------------------------------------------------------------------------
// Static device scratch (allocation-free rule: __device__ globals only)
// ---------------------------------------------------------------------------
__device__ __align__(16) float g_M [(size_t)ET * FD];   // means/query     [ET,1024]
__device__ __align__(16) float g_Y1[(size_t)ET * HD];   // layer-1 act     [ET, 512]
__device__ __align__(16) float g_Y2[(size_t)ET * HD];   // layer-2 act     [ET, 512]
__device__ __align__(16) float g_A2[(size_t)ET * FD];   // sigmoid(att)^2  [ET,1024]

__device__ __forceinline__ float* bufptr(int s) {
    switch (s) {
        case 0:  return g_M;
        case 1:  return g_Y1;
        case 2:  return g_Y2;
        default: return g_A2;
    }
}

// ---------------------------------------------------------------------------
// Kernel 1: per-episode class means (rows 0..24 -> 5 means, row 25 -> query)
// One block per episode, 256 threads over FD/4 float4s. Coalesced.
// ---------------------------------------------------------------------------
__global__ void __launch_bounds__(256) mean_kernel(const float* __restrict__ nf) {
    int b  = blockIdx.x;
    int f4 = threadIdx.x;                       // 0..255
    const float4* src = (const float4*)nf + (size_t)b * NN * (FD / 4);
    float4*       dst = (float4*)g_M    + (size_t)b * E6 * (FD / 4);

#pragma unroll
    for (int c = 0; c < 5; c++) {
        float4 s0 = src[(c * 5 + 0) * (FD / 4) + f4];
        float4 s1 = src[(c * 5 + 1) * (FD / 4) + f4];
        float4 s2 = src[(c * 5 + 2) * (FD / 4) + f4];
        float4 s3 = src[(c * 5 + 3) * (FD / 4) + f4];
        float4 s4 = src[(c * 5 + 4) * (FD / 4) + f4];
        float4 o;
        o.x = (s0.x + s1.x + s2.x + s3.x + s4.x) / 5.0f;
        o.y = (s0.y + s1.y + s2.y + s3.y + s4.y) / 5.0f;
        o.z = (s0.z + s1.z + s2.z + s3.z + s4.z) / 5.0f;
        o.w = (s0.w + s1.w + s2.w + s3.w + s4.w) / 5.0f;
        dst[c * (FD / 4) + f4] = o;
    }
    dst[5 * (FD / 4) + f4] = src[25 * (FD / 4) + f4];
}

// ---------------------------------------------------------------------------
// Simple tiled fp32 GEMM:  C[ET,NCOL] = A[ET,K] * W[NCOL,K]^T  + epilogue
// BM=64, BN=64, BK=16, 256 threads, 4x4 outputs per thread.
// Loader: thread tid loads ONE float4 of A (row lr, k lc..lc+3) and ONE of W.
// EPI 0/1: conv bias + BatchNorm (inference, unfolded) + leaky_relu(0.01).
// EPI 2:   conv bias + sigmoid, stores sigmoid^2.
// ---------------------------------------------------------------------------
template <int K, int NCOL, int EPI>
__global__ void __launch_bounds__(256) gemm_k(
    int asel, int csel,
    const float* __restrict__ W,
    const float* __restrict__ bias,
    const float* __restrict__ gamma,
    const float* __restrict__ beta,
    const float* __restrict__ rmean,
    const float* __restrict__ rvar)
{
    const float* A = bufptr(asel);
    float*       C = bufptr(csel);

    __shared__ __align__(16) float As[16][68];   // [k][m], padded row (272B = 17*16)
    __shared__ __align__(16) float Bs[16][68];   // [k][n]

    const int tid  = threadIdx.x;
    const int tx   = tid & 15;        // 0..15 -> cols tx*4 .. tx*4+3
    const int ty   = tid >> 4;        // 0..15 -> rows ty*4 .. ty*4+3
    const int row0 = blockIdx.x * 64;
    const int col0 = blockIdx.y * 64;

    float acc[4][4] = {};

    const int lr = tid >> 2;          // 0..63 : tile row loaded by this thread
    const int lc = (tid & 3) * 4;     // 0,4,8,12 : k offset within tile
    const float* Ap = A + (size_t)(row0 + lr) * K + lc;
    const float* Wp = W + (size_t)(col0 + lr) * K + lc;

    for (int kt = 0; kt < K; kt += 16) {
        float4 a = *(const float4*)(Ap + kt);
        float4 b = *(const float4*)(Wp + kt);
        As[lc + 0][lr] = a.x; As[lc + 1][lr] = a.y;
        As[lc + 2][lr] = a.z; As[lc + 3][lr] = a.w;
        Bs[lc + 0][lr] = b.x; Bs[lc + 1][lr] = b.y;
        Bs[lc + 2][lr] = b.z; Bs[lc + 3][lr] = b.w;
        __syncthreads();

#pragma unroll
        for (int k = 0; k < 16; k++) {
            float4 av = *(const float4*)&As[k][ty * 4];
            float4 bv = *(const float4*)&Bs[k][tx * 4];
            float am[4] = {av.x, av.y, av.z, av.w};
            float bn[4] = {bv.x, bv.y, bv.z, bv.w};
#pragma unroll
            for (int m = 0; m < 4; m++)
#pragma unroll
                for (int n = 0; n < 4; n++)
                    acc[m][n] += am[m] * bn[n];
        }
        __syncthreads();
    }

#pragma unroll
    for (int m = 0; m < 4; m++) {
        int r = row0 + ty * 4 + m;
        float v[4];
#pragma unroll
        for (int n = 0; n < 4; n++) {
            int h = col0 + tx * 4 + n;
            float y = acc[m][n] + bias[h];         // conv output (bias added)
            if (EPI == 2) {
                float sg = 1.0f / (1.0f + expf(-y));
                v[n] = sg * sg;                    // store attention^2
            } else {
                float sc = gamma[h] * rsqrtf(rvar[h] + 1e-5f);
                y = (y - rmean[h]) * sc + beta[h]; // inference BatchNorm
                v[n] = (y > 0.0f) ? y : 0.01f * y; // leaky relu
            }
        }
        float4 o; o.x = v[0]; o.y = v[1]; o.z = v[2]; o.w = v[3];
        *(float4*)(C + (size_t)r * NCOL + col0 + tx * 4) = o;
    }
}

// ---------------------------------------------------------------------------
// Kernel 5: per-episode 6x6 cosine similarity + broadcast to [2,26,26].
// One block (128 threads) per episode. Stage the 6 rows of M and A2 into
// smem in two 512-wide chunks. 36 ORDERED pairs distributed across 4 warps
// (9 pairs each); each pair reduces d, nij, nji with a lane-strided loop.
//   sim(i,j) = d / (sqrt(nij) * sqrt(nji))
//   d   = sum_f (a_i x_i)(a_j x_j),  nij = sum_f a_i x_i^2 a_j,
//   nji = sum_f a_j x_j^2 a_i        (a = attention^2 from g_A2)
// ---------------------------------------------------------------------------
__global__ void __launch_bounds__(128) sim_kernel(float* __restrict__ out) {
    const int b    = blockIdx.x;
    const int tid  = threadIdx.x;
    const int wid  = tid >> 5;
    const int lane = tid & 31;

    __shared__ float sM[E6][512];
    __shared__ float sA[E6][512];
    __shared__ float s_sim[36];

    const float* Mb = g_M  + (size_t)b * E6 * FD;
    const float* Ab = g_A2 + (size_t)b * E6 * FD;

    float d[9], nij[9], nji[9];
#pragma unroll
    for (int q = 0; q < 9; q++) { d[q] = 0.0f; nij[q] = 0.0f; nji[q] = 0.0f; }

    for (int half = 0; half < 2; half++) {
        __syncthreads();   // protect smem reuse across halves
        for (int idx = tid; idx < E6 * 512; idx += 128) {
            int row = idx >> 9;           // /512
            int col = idx & 511;          // %512
            sM[row][col] = Mb[row * FD + half * 512 + col];
            sA[row][col] = Ab[row * FD + half * 512 + col];
        }
        __syncthreads();

        int q = 0;
        for (int p = wid; p < 36; p += 4, q++) {
            int i = p / 6, j = p % 6;
            float dd = 0.0f, ni = 0.0f, nj = 0.0f;
            for (int f = lane; f < 512; f += 32) {
                float ai = sA[i][f], aj = sA[j][f];
                float xi = sM[i][f], xj = sM[j][f];
                float pi = ai * xi;
                float pj = aj * xj;
                dd += pi * pj;
                ni += pi * xi * aj;     // a_i x_i^2 a_j
                nj += pj * xj * ai;     // a_j x_j^2 a_i
            }
            d[q] += dd; nij[q] += ni; nji[q] += nj;
        }
    }

    // reduce each pair across the warp, write sim to smem
    {
        int q = 0;
        for (int p = wid; p < 36; p += 4, q++) {
            float dd = d[q], ni = nij[q], nj = nji[q];
#pragma unroll
            for (int off = 16; off > 0; off >>= 1) {
                dd += __shfl_xor_sync(0xffffffffu, dd, off);
                ni += __shfl_xor_sync(0xffffffffu, ni, off);
                nj += __shfl_xor_sync(0xffffffffu, nj, off);
            }
            if (lane == 0)
                s_sim[p] = dd / (sqrtf(ni) * sqrtf(nj));
        }
    }
    __syncthreads();

    // broadcast 6x6 -> [2,26,26], clip to [0,1]
    size_t base = (size_t)b * (2 * NN * NN);
    for (int idx = tid; idx < 2 * NN * NN; idx += 128) {
        int s = idx / (NN * NN);
        int r = idx - s * (NN * NN);
        int i = r / NN;
        int j = r - i * NN;
        int ci = (i < 25) ? (i / 5) : 5;
        int cj = (j < 25) ? (j / 5) : 5;
        float v = s_sim[ci * 6 + cj];
        if (s) v = 1.0f - v;
        out[base + idx] = fminf(fmaxf(v, 0.0f), 1.0f);
    }
}

// ---------------------------------------------------------------------------
// Launch (graph-capturable: kernel launches only, same stream, no allocs)
// ---------------------------------------------------------------------------
extern "C" void kernel_launch(void* const* d_in, const int* in_sizes, int n_in,
                              void* d_out, int out_size) {
    const float* nf  = (const float*)d_in[0];
    const float* w1  = (const float*)d_in[1];
    const float* b1  = (const float*)d_in[2];
    const float* g1  = (const float*)d_in[3];
    const float* be1 = (const float*)d_in[4];
    const float* m1  = (const float*)d_in[5];
    const float* v1  = (const float*)d_in[6];
    const float* w2  = (const float*)d_in[7];
    const float* b2  = (const float*)d_in[8];
    const float* g2  = (const float*)d_in[9];
    const float* be2 = (const float*)d_in[10];
    const float* m2  = (const float*)d_in[11];
    const float* v2  = (const float*)d_in[12];
    const float* w3  = (const float*)d_in[13];
    const float* b3  = (const float*)d_in[14];
    float* out = (float*)d_out;

    mean_kernel<<<NB, 256>>>(nf);

    // Y1 = leaky(bn1(M @ w1^T + b1))       [12288,1024] x [512,1024]^T
    gemm_k<FD, HD, 0><<<dim3(ET / 64, HD / 64), 256>>>(
        0, 1, w1, b1, g1, be1, m1, v1);

    // Y2 = leaky(bn2(Y1 @ w2^T + b2))      [12288,512] x [512,512]^T
    gemm_k<HD, HD, 1><<<dim3(ET / 64, HD / 64), 256>>>(
        1, 2, w2, b2, g2, be2, m2, v2);

    // A2 = sigmoid(Y2 @ w3^T + b3)^2       [12288,512] x [1024,512]^T
    gemm_k<HD, FD, 2><<<dim3(ET / 64, FD / 64), 256>>>(
        2, 3, w3, b3, nullptr, nullptr, nullptr, nullptr);

    // per-episode 6x6 cosine sim -> broadcast [2,26,26]
    sim_kernel<<<NB, 128>>>(out);
}

// round 8
// speedup vs baseline: 1.8316x; 1.8316x over previous
#include <cuda_runtime.h>
#include <cuda_bf16.h>
#include <math.h>
#include <cstdint>

// Problem constants
#define NB     2048            // batch (episodes)
#define NN     26              // nodes per episode
#define FD     1024            // feature dim
#define HD     512             // hidden dim
#define E6     6               // distinct rows per episode (5 class means + query)
#define ET     (NB * E6)       // 12288 effective GEMM rows

// ---------------------------------------------------------------------------
// Static device scratch (fp32 everywhere; splits derived in registers)
// ---------------------------------------------------------------------------
__device__ __align__(16) float g_M [(size_t)ET * FD];   // means/query  [ET,1024]
__device__ __align__(16) float g_Y1[(size_t)ET * HD];   // layer-1 act  [ET, 512]
__device__ __align__(16) float g_Y2[(size_t)ET * HD];   // layer-2 act  [ET, 512]
__device__ __align__(16) float g_A2[(size_t)ET * FD];   // att^2        [ET,1024]

// ---------------------------------------------------------------------------
// PTX helpers (plain sm_103-legal: mma.sync / cp.async only)
// ---------------------------------------------------------------------------
__device__ __forceinline__ uint32_t smem_u32(const void* p) {
    uint32_t a;
    asm("{ .reg .u64 t; cvta.to.shared.u64 t, %1; cvt.u32.u64 %0, t; }"
        : "=r"(a) : "l"(p));
    return a;
}
__device__ __forceinline__ void cp_async16(uint32_t dst, const void* src) {
    asm volatile("cp.async.cg.shared.global [%0], [%1], 16;"
                 :: "r"(dst), "l"(src) : "memory");
}
__device__ __forceinline__ void cp_commit() {
    asm volatile("cp.async.commit_group;" ::: "memory");
}
template <int N>
__device__ __forceinline__ void cp_wait() {
    asm volatile("cp.async.wait_group %0;" :: "n"(N) : "memory");
}
__device__ __forceinline__ void mma16816(float* c, const uint32_t* a,
                                         const uint32_t* b) {
    asm volatile(
        "mma.sync.aligned.m16n8k16.row.col.f32.bf16.bf16.f32 "
        "{%0,%1,%2,%3}, {%4,%5,%6,%7}, {%8,%9}, {%0,%1,%2,%3};"
        : "+f"(c[0]), "+f"(c[1]), "+f"(c[2]), "+f"(c[3])
        : "r"(a[0]), "r"(a[1]), "r"(a[2]), "r"(a[3]), "r"(b[0]), "r"(b[1]));
}
// pack float2 -> bf16x2 (x -> low half = first k element)
__device__ __forceinline__ uint32_t hi_pack(float2 v) {
    __nv_bfloat162 h = __float22bfloat162_rn(v);
    return *reinterpret_cast<uint32_t*>(&h);
}
__device__ __forceinline__ uint32_t lo_pack(float2 v, uint32_t hi) {
    __nv_bfloat162 h = *reinterpret_cast<__nv_bfloat162*>(&hi);
    float2 hf = __bfloat1622float2(h);
    float2 r; r.x = v.x - hf.x; r.y = v.y - hf.y;
    __nv_bfloat162 l = __float22bfloat162_rn(r);
    return *reinterpret_cast<uint32_t*>(&l);
}

// ---------------------------------------------------------------------------
// Kernel 1: per-episode class means (R3-proven fp32 version)
// ---------------------------------------------------------------------------
__global__ void __launch_bounds__(256) mean_kernel(const float* __restrict__ nf) {
    int b  = blockIdx.x;
    int f4 = threadIdx.x;                       // 0..255
    const float4* src = (const float4*)nf + (size_t)b * NN * (FD / 4);
    float4*       dst = (float4*)g_M    + (size_t)b * E6 * (FD / 4);

#pragma unroll
    for (int c = 0; c < 5; c++) {
        float4 s0 = src[(c * 5 + 0) * (FD / 4) + f4];
        float4 s1 = src[(c * 5 + 1) * (FD / 4) + f4];
        float4 s2 = src[(c * 5 + 2) * (FD / 4) + f4];
        float4 s3 = src[(c * 5 + 3) * (FD / 4) + f4];
        float4 s4 = src[(c * 5 + 4) * (FD / 4) + f4];
        float4 o;
        o.x = (s0.x + s1.x + s2.x + s3.x + s4.x) / 5.0f;
        o.y = (s0.y + s1.y + s2.y + s3.y + s4.y) / 5.0f;
        o.z = (s0.z + s1.z + s2.z + s3.z + s4.z) / 5.0f;
        o.w = (s0.w + s1.w + s2.w + s3.w + s4.w) / 5.0f;
        dst[c * (FD / 4) + f4] = o;
    }
    dst[5 * (FD / 4) + f4] = src[25 * (FD / 4) + f4];
}

// ---------------------------------------------------------------------------
// 4-term split-bf16 HMMA GEMM, fp32 source data, fp32-accurate result.
//   C[ET,NCOL] = A[ET,K] * W[NCOL,K]^T  (+ fused epilogue)
// Tile 128x128, 256 threads (8 warps 2x4), warp tile 64x32 (m16n8k16).
// fp32 A/W chunks (128x32) staged in smem via cp.async (single-buffered).
// Fragments loaded manually per PTX ISA tables (LDS.64), converted in regs:
//   hi = bf16(x), lo = bf16(x - hi);   acc += hi*wh + lo*wh + hi*wl + lo*wl
// LAYER 1/2: bias+BN+leaky -> fp32 Y.   LAYER 3: sigmoid^2 -> fp32 A2.
// ---------------------------------------------------------------------------
#define RPAD 40                 // floats per smem row (160B): conflict-free

template <int K, int NCOL, int LAYER>
__global__ void __launch_bounds__(256, 2) gemm_mma4(
    const float* __restrict__ Asrc,
    const float* __restrict__ W,
    float*       __restrict__ Cdst,
    const float* __restrict__ bias,
    const float* __restrict__ gamma,
    const float* __restrict__ beta,
    const float* __restrict__ rmean,
    const float* __restrict__ rvar)
{
    __shared__ __align__(16) float sbuf[2][128 * RPAD];   // [A|B], 160B rows

    const int tid  = threadIdx.x;
    const int wid  = tid >> 5;
    const int lane = tid & 31;
    const int wrow = wid >> 2;           // 0..1
    const int wcol = wid & 3;            // 0..3
    const int g    = lane >> 2;          // 0..7 groupID
    const int tg   = lane & 3;           // 0..3 thread-in-group
    const int row0 = blockIdx.x * 128;
    const int col0 = blockIdx.y * 128;

    float* sA = sbuf[0];
    float* sB = sbuf[1];
    const uint32_t sA32 = smem_u32(sA);
    const uint32_t sB32 = smem_u32(sB);

    float acc[4][4][4];
#pragma unroll
    for (int mt = 0; mt < 4; mt++)
#pragma unroll
        for (int nt = 0; nt < 4; nt++)
#pragma unroll
            for (int e = 0; e < 4; e++) acc[mt][nt][e] = 0.0f;

    for (int kb = 0; kb < K; kb += 32) {
        // ---- load 128x32 fp32 A and B chunks (8 x 16B segs per row) ----
#pragma unroll
        for (int i = 0; i < 4; i++) {
            int idx = i * 256 + tid;          // 0..1023
            int r   = idx >> 3;
            int s   = idx & 7;
            uint32_t so = (uint32_t)(r * RPAD + s * 4) * 4u;
            cp_async16(sA32 + so, Asrc + (size_t)(row0 + r) * K + kb + s * 4);
            cp_async16(sB32 + so, W    + (size_t)(col0 + r) * K + kb + s * 4);
        }
        cp_commit();
        cp_wait<0>();
        __syncthreads();

#pragma unroll
        for (int ks = 0; ks < 2; ks++) {
            // ---- B fragments (4 n-tiles), convert once ----
            uint32_t bh[4][2], bl[4][2];
#pragma unroll
            for (int nt = 0; nt < 4; nt++) {
                const float* p = sB + (wcol * 32 + nt * 8 + g) * RPAD
                                    + ks * 16 + 2 * tg;
                float2 q0 = *(const float2*)(p);       // k, k+1
                float2 q1 = *(const float2*)(p + 8);   // k+8, k+9
                bh[nt][0] = hi_pack(q0); bl[nt][0] = lo_pack(q0, bh[nt][0]);
                bh[nt][1] = hi_pack(q1); bl[nt][1] = lo_pack(q1, bh[nt][1]);
            }
            // ---- A fragments per m-tile, 4 mma terms per (mt,nt) ----
#pragma unroll
            for (int mt = 0; mt < 4; mt++) {
                const float* p = sA + (wrow * 64 + mt * 16 + g) * RPAD
                                    + ks * 16 + 2 * tg;
                float2 f0 = *(const float2*)(p);               // row g   , k
                float2 f1 = *(const float2*)(p + 8 * RPAD);    // row g+8 , k
                float2 f2 = *(const float2*)(p + 8);           // row g   , k+8
                float2 f3 = *(const float2*)(p + 8 * RPAD + 8);
                uint32_t ah[4], al[4];
                ah[0] = hi_pack(f0); al[0] = lo_pack(f0, ah[0]);
                ah[1] = hi_pack(f1); al[1] = lo_pack(f1, ah[1]);
                ah[2] = hi_pack(f2); al[2] = lo_pack(f2, ah[2]);
                ah[3] = hi_pack(f3); al[3] = lo_pack(f3, ah[3]);
#pragma unroll
                for (int nt = 0; nt < 4; nt++) {
                    mma16816(acc[mt][nt], ah, bh[nt]);
                    mma16816(acc[mt][nt], al, bh[nt]);
                    mma16816(acc[mt][nt], ah, bl[nt]);
                    mma16816(acc[mt][nt], al, bl[nt]);
                }
            }
        }
        __syncthreads();
    }

    // -------- fused epilogue --------
    const int er0 = row0 + wrow * 64 + g;               // +mt*16, +8 upper half
    const int ec0 = col0 + wcol * 32 + 2 * tg;          // +nt*8

#pragma unroll
    for (int nt = 0; nt < 4; nt++) {
        const int h0 = ec0 + nt * 8;
        float sc0, sh0 = 0.f, sc1, sh1 = 0.f;
        if (LAYER == 3) {
            sc0 = bias[h0]; sc1 = bias[h0 + 1];
        } else {
            float s0 = gamma[h0] * rsqrtf(rvar[h0] + 1e-5f);
            float s1 = gamma[h0 + 1] * rsqrtf(rvar[h0 + 1] + 1e-5f);
            sc0 = s0; sh0 = (bias[h0] - rmean[h0]) * s0 + beta[h0];
            sc1 = s1; sh1 = (bias[h0 + 1] - rmean[h0 + 1]) * s1 + beta[h0 + 1];
        }
#pragma unroll
        for (int mt = 0; mt < 4; mt++) {
#pragma unroll
            for (int half = 0; half < 2; half++) {
                int r = er0 + mt * 16 + half * 8;
                float v0 = acc[mt][nt][half * 2 + 0];
                float v1 = acc[mt][nt][half * 2 + 1];
                float2 o;
                if (LAYER == 3) {
                    float y0 = v0 + sc0, y1 = v1 + sc1;
                    float g0 = 1.0f / (1.0f + expf(-y0));
                    float g1 = 1.0f / (1.0f + expf(-y1));
                    o.x = g0 * g0; o.y = g1 * g1;
                } else {
                    float y0 = v0 * sc0 + sh0;     // BN folded (bias inside sh)
                    float y1 = v1 * sc1 + sh1;
                    o.x = (y0 > 0.0f) ? y0 : 0.01f * y0;
                    o.y = (y1 > 0.0f) ? y1 : 0.01f * y1;
                }
                *(float2*)(Cdst + (size_t)r * NCOL + h0) = o;
            }
        }
    }
}

// ---------------------------------------------------------------------------
// Kernel: per-episode 6x6 cosine similarity + broadcast (R3-proven)
// ---------------------------------------------------------------------------
__global__ void __launch_bounds__(128) sim_kernel(float* __restrict__ out) {
    const int b    = blockIdx.x;
    const int tid  = threadIdx.x;
    const int wid  = tid >> 5;
    const int lane = tid & 31;

    __shared__ float sM[E6][512];
    __shared__ float sA[E6][512];
    __shared__ float s_sim[36];

    const float* Mb = g_M  + (size_t)b * E6 * FD;
    const float* Ab = g_A2 + (size_t)b * E6 * FD;

    float d[9], nij[9], nji[9];
#pragma unroll
    for (int q = 0; q < 9; q++) { d[q] = 0.0f; nij[q] = 0.0f; nji[q] = 0.0f; }

    for (int half = 0; half < 2; half++) {
        __syncthreads();
        for (int idx = tid; idx < E6 * 512; idx += 128) {
            int row = idx >> 9;
            int col = idx & 511;
            sM[row][col] = Mb[row * FD + half * 512 + col];
            sA[row][col] = Ab[row * FD + half * 512 + col];
        }
        __syncthreads();

        int q = 0;
        for (int p = wid; p < 36; p += 4, q++) {
            int i = p / 6, j = p % 6;
            float dd = 0.0f, ni = 0.0f, nj = 0.0f;
            for (int f = lane; f < 512; f += 32) {
                float ai = sA[i][f], aj = sA[j][f];
                float xi = sM[i][f], xj = sM[j][f];
                float pi = ai * xi;
                float pj = aj * xj;
                dd += pi * pj;
                ni += pi * xi * aj;
                nj += pj * xj * ai;
            }
            d[q] += dd; nij[q] += ni; nji[q] += nj;
        }
    }

    {
        int q = 0;
        for (int p = wid; p < 36; p += 4, q++) {
            float dd = d[q], ni = nij[q], nj = nji[q];
#pragma unroll
            for (int off = 16; off > 0; off >>= 1) {
                dd += __shfl_xor_sync(0xffffffffu, dd, off);
                ni += __shfl_xor_sync(0xffffffffu, ni, off);
                nj += __shfl_xor_sync(0xffffffffu, nj, off);
            }
            if (lane == 0)
                s_sim[p] = dd / (sqrtf(ni) * sqrtf(nj));
        }
    }
    __syncthreads();

    size_t base = (size_t)b * (2 * NN * NN);
    for (int idx = tid; idx < 2 * NN * NN; idx += 128) {
        int s = idx / (NN * NN);
        int rr = idx - s * (NN * NN);
        int i = rr / NN;
        int j = rr - i * NN;
        int ci = (i < 25) ? (i / 5) : 5;
        int cj = (j < 25) ? (j / 5) : 5;
        float v = s_sim[ci * 6 + cj];
        if (s) v = 1.0f - v;
        out[base + idx] = fminf(fmaxf(v, 0.0f), 1.0f);
    }
}

// ---------------------------------------------------------------------------
// Launch (graph-capturable)
// ---------------------------------------------------------------------------
extern "C" void kernel_launch(void* const* d_in, const int* in_sizes, int n_in,
                              void* d_out, int out_size) {
    const float* nf  = (const float*)d_in[0];
    const float* w1  = (const float*)d_in[1];
    const float* b1  = (const float*)d_in[2];
    const float* g1  = (const float*)d_in[3];
    const float* be1 = (const float*)d_in[4];
    const float* m1  = (const float*)d_in[5];
    const float* v1  = (const float*)d_in[6];
    const float* w2  = (const float*)d_in[7];
    const float* b2  = (const float*)d_in[8];
    const float* g2  = (const float*)d_in[9];
    const float* be2 = (const float*)d_in[10];
    const float* m2  = (const float*)d_in[11];
    const float* v2  = (const float*)d_in[12];
    const float* w3  = (const float*)d_in[13];
    const float* b3  = (const float*)d_in[14];
    float* out = (float*)d_out;

    float* pM  = nullptr; cudaGetSymbolAddress((void**)&pM,  g_M);
    float* pY1 = nullptr; cudaGetSymbolAddress((void**)&pY1, g_Y1);
    float* pY2 = nullptr; cudaGetSymbolAddress((void**)&pY2, g_Y2);
    float* pA2 = nullptr; cudaGetSymbolAddress((void**)&pA2, g_A2);

    mean_kernel<<<NB, 256>>>(nf);

    // Y1 = leaky(bn1(M @ w1^T + b1))        [12288,1024] x [512,1024]^T
    gemm_mma4<FD, HD, 1><<<dim3(ET / 128, HD / 128), 256>>>(
        pM, w1, pY1, b1, g1, be1, m1, v1);
    // Y2 = leaky(bn2(Y1 @ w2^T + b2))       [12288,512] x [512,512]^T
    gemm_mma4<HD, HD, 2><<<dim3(ET / 128, HD / 128), 256>>>(
        pY1, w2, pY2, b2, g2, be2, m2, v2);
    // A2 = sigmoid(Y2 @ w3^T + b3)^2        [12288,512] x [1024,512]^T
    gemm_mma4<HD, FD, 3><<<dim3(ET / 128, FD / 128), 256>>>(
        pY2, w3, pA2, b3, nullptr, nullptr, nullptr, nullptr);

    // per-episode 6x6 cosine sim -> broadcast [2,26,26]
    sim_kernel<<<NB, 128>>>(out);
}

// round 9
// speedup vs baseline: 2.1376x; 1.1671x over previous
#include <cuda_runtime.h>
#include <cuda_bf16.h>
#include <math.h>
#include <cstdint>

// Problem constants
#define NB     2048            // batch (episodes)
#define NN     26              // nodes per episode
#define FD     1024            // feature dim
#define HD     512             // hidden dim
#define E6     6               // distinct rows per episode (5 class means + query)
#define ET     (NB * E6)       // 12288 effective GEMM rows

// ---------------------------------------------------------------------------
// Static device scratch (fp32 everywhere; splits derived in registers)
// ---------------------------------------------------------------------------
__device__ __align__(16) float g_M [(size_t)ET * FD];   // means/query  [ET,1024]
__device__ __align__(16) float g_Y1[(size_t)ET * HD];   // layer-1 act  [ET, 512]
__device__ __align__(16) float g_Y2[(size_t)ET * HD];   // layer-2 act  [ET, 512]
__device__ __align__(16) float g_A2[(size_t)ET * FD];   // att^2        [ET,1024]

// ---------------------------------------------------------------------------
// PTX helpers (plain sm_103-legal: mma.sync / cp.async only)
// ---------------------------------------------------------------------------
__device__ __forceinline__ uint32_t smem_u32(const void* p) {
    uint32_t a;
    asm("{ .reg .u64 t; cvta.to.shared.u64 t, %1; cvt.u32.u64 %0, t; }"
        : "=r"(a) : "l"(p));
    return a;
}
__device__ __forceinline__ void cp_async16(uint32_t dst, const void* src) {
    asm volatile("cp.async.cg.shared.global [%0], [%1], 16;"
                 :: "r"(dst), "l"(src) : "memory");
}
__device__ __forceinline__ void cp_commit() {
    asm volatile("cp.async.commit_group;" ::: "memory");
}
template <int N>
__device__ __forceinline__ void cp_wait() {
    asm volatile("cp.async.wait_group %0;" :: "n"(N) : "memory");
}
__device__ __forceinline__ void mma16816(float* c, const uint32_t* a,
                                         const uint32_t* b) {
    asm volatile(
        "mma.sync.aligned.m16n8k16.row.col.f32.bf16.bf16.f32 "
        "{%0,%1,%2,%3}, {%4,%5,%6,%7}, {%8,%9}, {%0,%1,%2,%3};"
        : "+f"(c[0]), "+f"(c[1]), "+f"(c[2]), "+f"(c[3])
        : "r"(a[0]), "r"(a[1]), "r"(a[2]), "r"(a[3]), "r"(b[0]), "r"(b[1]));
}
// pack float2 -> bf16x2 (x -> low half = first k element)
__device__ __forceinline__ uint32_t hi_pack(float2 v) {
    __nv_bfloat162 h = __float22bfloat162_rn(v);
    return *reinterpret_cast<uint32_t*>(&h);
}
__device__ __forceinline__ uint32_t lo_pack(float2 v, uint32_t hi) {
    __nv_bfloat162 h = *reinterpret_cast<__nv_bfloat162*>(&hi);
    float2 hf = __bfloat1622float2(h);
    float2 r; r.x = v.x - hf.x; r.y = v.y - hf.y;
    __nv_bfloat162 l = __float22bfloat162_rn(r);
    return *reinterpret_cast<uint32_t*>(&l);
}

// ---------------------------------------------------------------------------
// Kernel 1: per-episode class means (proven fp32 version)
// ---------------------------------------------------------------------------
__global__ void __launch_bounds__(256) mean_kernel(const float* __restrict__ nf) {
    int b  = blockIdx.x;
    int f4 = threadIdx.x;                       // 0..255
    const float4* src = (const float4*)nf + (size_t)b * NN * (FD / 4);
    float4*       dst = (float4*)g_M    + (size_t)b * E6 * (FD / 4);

#pragma unroll
    for (int c = 0; c < 5; c++) {
        float4 s0 = src[(c * 5 + 0) * (FD / 4) + f4];
        float4 s1 = src[(c * 5 + 1) * (FD / 4) + f4];
        float4 s2 = src[(c * 5 + 2) * (FD / 4) + f4];
        float4 s3 = src[(c * 5 + 3) * (FD / 4) + f4];
        float4 s4 = src[(c * 5 + 4) * (FD / 4) + f4];
        float4 o;
        o.x = (s0.x + s1.x + s2.x + s3.x + s4.x) / 5.0f;
        o.y = (s0.y + s1.y + s2.y + s3.y + s4.y) / 5.0f;
        o.z = (s0.z + s1.z + s2.z + s3.z + s4.z) / 5.0f;
        o.w = (s0.w + s1.w + s2.w + s3.w + s4.w) / 5.0f;
        dst[c * (FD / 4) + f4] = o;
    }
    dst[5 * (FD / 4) + f4] = src[25 * (FD / 4) + f4];
}

// ---------------------------------------------------------------------------
// 3-term split-bf16 HMMA GEMM, fp32 src, fp32-accurate (~3e-5 rel):
//   C[ET,NCOL] = A[ET,K] * W[NCOL,K]^T  (+ fused epilogue)
// Tile 128x128, 256 threads (8 warps 2x4), warp tile 64x32 (m16n8k16).
// fp32 A/W chunks (128x32) DOUBLE-BUFFERED in dynamic smem via cp.async.
// Fragments loaded manually per PTX ISA tables (LDS.64), converted in regs:
//   hi = bf16(x), lo = bf16(x - hi);   acc += hi*wh + lo*wh + hi*wl
// LAYER 1/2: bias+BN+leaky -> fp32 Y.   LAYER 3: sigmoid^2 -> fp32 A2.
// ---------------------------------------------------------------------------
#define RPAD 40                 // floats per smem row (160B): conflict-free
#define TILEF (128 * RPAD)      // floats per tile
#define GEMM_SMEM_BYTES (2 * 2 * TILEF * 4)   // 81920

template <int K, int NCOL, int LAYER>
__global__ void __launch_bounds__(256, 2) gemm_mma3(
    const float* __restrict__ Asrc,
    const float* __restrict__ W,
    float*       __restrict__ Cdst,
    const float* __restrict__ bias,
    const float* __restrict__ gamma,
    const float* __restrict__ beta,
    const float* __restrict__ rmean,
    const float* __restrict__ rvar)
{
    extern __shared__ __align__(16) float sbuf[];   // [2 buf][A|B][128*RPAD]

    constexpr int NCHUNK = K / 32;

    const int tid  = threadIdx.x;
    const int wid  = tid >> 5;
    const int lane = tid & 31;
    const int wrow = wid >> 2;           // 0..1
    const int wcol = wid & 3;            // 0..3
    const int g    = lane >> 2;          // 0..7 groupID
    const int tg   = lane & 3;           // 0..3 thread-in-group
    const int row0 = blockIdx.x * 128;
    const int col0 = blockIdx.y * 128;

    // cp.async issue of one 128x32 fp32 A chunk + B chunk into buffer `buf`
    auto issue_chunk = [&](int kb, int buf) {
        const uint32_t a32 = smem_u32(sbuf + (size_t)buf * 2 * TILEF);
        const uint32_t b32 = a32 + TILEF * 4;
#pragma unroll
        for (int i = 0; i < 4; i++) {
            int idx = i * 256 + tid;          // 0..1023
            int r   = idx >> 3;
            int s   = idx & 7;
            uint32_t so = (uint32_t)(r * RPAD + s * 4) * 4u;
            cp_async16(a32 + so, Asrc + (size_t)(row0 + r) * K + kb + s * 4);
            cp_async16(b32 + so, W    + (size_t)(col0 + r) * K + kb + s * 4);
        }
        cp_commit();
    };

    float acc[4][4][4];
#pragma unroll
    for (int mt = 0; mt < 4; mt++)
#pragma unroll
        for (int nt = 0; nt < 4; nt++)
#pragma unroll
            for (int e = 0; e < 4; e++) acc[mt][nt][e] = 0.0f;

    issue_chunk(0, 0);

    for (int cc = 0; cc < NCHUNK; cc++) {
        const int buf = cc & 1;
        if (cc + 1 < NCHUNK) { issue_chunk((cc + 1) * 32, buf ^ 1); cp_wait<1>(); }
        else                 { cp_wait<0>(); }
        __syncthreads();

        const float* sA = sbuf + (size_t)buf * 2 * TILEF;
        const float* sB = sA + TILEF;

#pragma unroll
        for (int ks = 0; ks < 2; ks++) {
            // ---- B fragments (4 n-tiles), convert once per ks ----
            uint32_t bh[4][2], bl[4][2];
#pragma unroll
            for (int nt = 0; nt < 4; nt++) {
                const float* p = sB + (wcol * 32 + nt * 8 + g) * RPAD
                                    + ks * 16 + 2 * tg;
                float2 q0 = *(const float2*)(p);       // k, k+1
                float2 q1 = *(const float2*)(p + 8);   // k+8, k+9
                bh[nt][0] = hi_pack(q0); bl[nt][0] = lo_pack(q0, bh[nt][0]);
                bh[nt][1] = hi_pack(q1); bl[nt][1] = lo_pack(q1, bh[nt][1]);
            }
            // ---- A fragments per m-tile, 3 mma terms per (mt,nt) ----
#pragma unroll
            for (int mt = 0; mt < 4; mt++) {
                const float* p = sA + (wrow * 64 + mt * 16 + g) * RPAD
                                    + ks * 16 + 2 * tg;
                float2 f0 = *(const float2*)(p);               // row g   , k
                float2 f1 = *(const float2*)(p + 8 * RPAD);    // row g+8 , k
                float2 f2 = *(const float2*)(p + 8);           // row g   , k+8
                float2 f3 = *(const float2*)(p + 8 * RPAD + 8);
                uint32_t ah[4], al[4];
                ah[0] = hi_pack(f0); al[0] = lo_pack(f0, ah[0]);
                ah[1] = hi_pack(f1); al[1] = lo_pack(f1, ah[1]);
                ah[2] = hi_pack(f2); al[2] = lo_pack(f2, ah[2]);
                ah[3] = hi_pack(f3); al[3] = lo_pack(f3, ah[3]);
#pragma unroll
                for (int nt = 0; nt < 4; nt++) {
                    mma16816(acc[mt][nt], ah, bh[nt]);
                    mma16816(acc[mt][nt], al, bh[nt]);
                    mma16816(acc[mt][nt], ah, bl[nt]);
                }
            }
        }
        __syncthreads();   // WAR guard: buf fully consumed before re-issue
    }

    // -------- fused epilogue --------
    const int er0 = row0 + wrow * 64 + g;               // +mt*16, +8 upper half
    const int ec0 = col0 + wcol * 32 + 2 * tg;          // +nt*8

#pragma unroll
    for (int nt = 0; nt < 4; nt++) {
        const int h0 = ec0 + nt * 8;
        float sc0, sh0 = 0.f, sc1, sh1 = 0.f;
        if (LAYER == 3) {
            sc0 = bias[h0]; sc1 = bias[h0 + 1];
        } else {
            float s0 = gamma[h0] * rsqrtf(rvar[h0] + 1e-5f);
            float s1 = gamma[h0 + 1] * rsqrtf(rvar[h0 + 1] + 1e-5f);
            sc0 = s0; sh0 = (bias[h0] - rmean[h0]) * s0 + beta[h0];
            sc1 = s1; sh1 = (bias[h0 + 1] - rmean[h0 + 1]) * s1 + beta[h0 + 1];
        }
#pragma unroll
        for (int mt = 0; mt < 4; mt++) {
#pragma unroll
            for (int half = 0; half < 2; half++) {
                int r = er0 + mt * 16 + half * 8;
                float v0 = acc[mt][nt][half * 2 + 0];
                float v1 = acc[mt][nt][half * 2 + 1];
                float2 o;
                if (LAYER == 3) {
                    float y0 = v0 + sc0, y1 = v1 + sc1;
                    float g0 = 1.0f / (1.0f + expf(-y0));
                    float g1 = 1.0f / (1.0f + expf(-y1));
                    o.x = g0 * g0; o.y = g1 * g1;
                } else {
                    float y0 = v0 * sc0 + sh0;     // BN folded (bias inside sh)
                    float y1 = v1 * sc1 + sh1;
                    o.x = (y0 > 0.0f) ? y0 : 0.01f * y0;
                    o.y = (y1 > 0.0f) ? y1 : 0.01f * y1;
                }
                *(float2*)(Cdst + (size_t)r * NCOL + h0) = o;
            }
        }
    }
}

// ---------------------------------------------------------------------------
// Kernel: per-episode 6x6 cosine similarity + broadcast (proven)
// ---------------------------------------------------------------------------
__global__ void __launch_bounds__(128) sim_kernel(float* __restrict__ out) {
    const int b    = blockIdx.x;
    const int tid  = threadIdx.x;
    const int wid  = tid >> 5;
    const int lane = tid & 31;

    __shared__ float sM[E6][512];
    __shared__ float sA[E6][512];
    __shared__ float s_sim[36];

    const float* Mb = g_M  + (size_t)b * E6 * FD;
    const float* Ab = g_A2 + (size_t)b * E6 * FD;

    float d[9], nij[9], nji[9];
#pragma unroll
    for (int q = 0; q < 9; q++) { d[q] = 0.0f; nij[q] = 0.0f; nji[q] = 0.0f; }

    for (int half = 0; half < 2; half++) {
        __syncthreads();
        for (int idx = tid; idx < E6 * 512; idx += 128) {
            int row = idx >> 9;
            int col = idx & 511;
            sM[row][col] = Mb[row * FD + half * 512 + col];
            sA[row][col] = Ab[row * FD + half * 512 + col];
        }
        __syncthreads();

        int q = 0;
        for (int p = wid; p < 36; p += 4, q++) {
            int i = p / 6, j = p % 6;
            float dd = 0.0f, ni = 0.0f, nj = 0.0f;
            for (int f = lane; f < 512; f += 32) {
                float ai = sA[i][f], aj = sA[j][f];
                float xi = sM[i][f], xj = sM[j][f];
                float pi = ai * xi;
                float pj = aj * xj;
                dd += pi * pj;
                ni += pi * xi * aj;
                nj += pj * xj * ai;
            }
            d[q] += dd; nij[q] += ni; nji[q] += nj;
        }
    }

    {
        int q = 0;
        for (int p = wid; p < 36; p += 4, q++) {
            float dd = d[q], ni = nij[q], nj = nji[q];
#pragma unroll
            for (int off = 16; off > 0; off >>= 1) {
                dd += __shfl_xor_sync(0xffffffffu, dd, off);
                ni += __shfl_xor_sync(0xffffffffu, ni, off);
                nj += __shfl_xor_sync(0xffffffffu, nj, off);
            }
            if (lane == 0)
                s_sim[p] = dd / (sqrtf(ni) * sqrtf(nj));
        }
    }
    __syncthreads();

    size_t base = (size_t)b * (2 * NN * NN);
    for (int idx = tid; idx < 2 * NN * NN; idx += 128) {
        int s = idx / (NN * NN);
        int rr = idx - s * (NN * NN);
        int i = rr / NN;
        int j = rr - i * NN;
        int ci = (i < 25) ? (i / 5) : 5;
        int cj = (j < 25) ? (j / 5) : 5;
        float v = s_sim[ci * 6 + cj];
        if (s) v = 1.0f - v;
        out[base + idx] = fminf(fmaxf(v, 0.0f), 1.0f);
    }
}

// ---------------------------------------------------------------------------
// Launch (graph-capturable: kernel launches only; attribute set is host-side)
// ---------------------------------------------------------------------------
extern "C" void kernel_launch(void* const* d_in, const int* in_sizes, int n_in,
                              void* d_out, int out_size) {
    const float* nf  = (const float*)d_in[0];
    const float* w1  = (const float*)d_in[1];
    const float* b1  = (const float*)d_in[2];
    const float* g1  = (const float*)d_in[3];
    const float* be1 = (const float*)d_in[4];
    const float* m1  = (const float*)d_in[5];
    const float* v1  = (const float*)d_in[6];
    const float* w2  = (const float*)d_in[7];
    const float* b2  = (const float*)d_in[8];
    const float* g2  = (const float*)d_in[9];
    const float* be2 = (const float*)d_in[10];
    const float* m2  = (const float*)d_in[11];
    const float* v2  = (const float*)d_in[12];
    const float* w3  = (const float*)d_in[13];
    const float* b3  = (const float*)d_in[14];
    float* out = (float*)d_out;

    float* pM  = nullptr; cudaGetSymbolAddress((void**)&pM,  g_M);
    float* pY1 = nullptr; cudaGetSymbolAddress((void**)&pY1, g_Y1);
    float* pY2 = nullptr; cudaGetSymbolAddress((void**)&pY2, g_Y2);
    float* pA2 = nullptr; cudaGetSymbolAddress((void**)&pA2, g_A2);

    // opt-in to 80KB dynamic smem for the GEMMs (idempotent host calls)
    cudaFuncSetAttribute(gemm_mma3<FD, HD, 1>,
                         cudaFuncAttributeMaxDynamicSharedMemorySize,
                         GEMM_SMEM_BYTES);
    cudaFuncSetAttribute(gemm_mma3<HD, HD, 2>,
                         cudaFuncAttributeMaxDynamicSharedMemorySize,
                         GEMM_SMEM_BYTES);
    cudaFuncSetAttribute(gemm_mma3<HD, FD, 3>,
                         cudaFuncAttributeMaxDynamicSharedMemorySize,
                         GEMM_SMEM_BYTES);

    mean_kernel<<<NB, 256>>>(nf);

    // Y1 = leaky(bn1(M @ w1^T + b1))        [12288,1024] x [512,1024]^T
    gemm_mma3<FD, HD, 1><<<dim3(ET / 128, HD / 128), 256, GEMM_SMEM_BYTES>>>(
        pM, w1, pY1, b1, g1, be1, m1, v1);
    // Y2 = leaky(bn2(Y1 @ w2^T + b2))       [12288,512] x [512,512]^T
    gemm_mma3<HD, HD, 2><<<dim3(ET / 128, HD / 128), 256, GEMM_SMEM_BYTES>>>(
        pY1, w2, pY2, b2, g2, be2, m2, v2);
    // A2 = sigmoid(Y2 @ w3^T + b3)^2        [12288,512] x [1024,512]^T
    gemm_mma3<HD, FD, 3><<<dim3(ET / 128, FD / 128), 256, GEMM_SMEM_BYTES>>>(
        pY2, w3, pA2, b3, nullptr, nullptr, nullptr, nullptr);

    // per-episode 6x6 cosine sim -> broadcast [2,26,26]
    sim_kernel<<<NB, 128>>>(out);
}

// round 10
// speedup vs baseline: 2.2153x; 1.0364x over previous
#include <cuda_runtime.h>
#include <cuda_bf16.h>
#include <math.h>
#include <cstdint>

// Problem constants
#define NB     2048            // batch (episodes)
#define NN     26              // nodes per episode
#define FD     1024            // feature dim
#define HD     512             // hidden dim
#define E6     6               // distinct rows per episode (5 class means + query)
#define ET     (NB * E6)       // 12288 effective GEMM rows

// ---------------------------------------------------------------------------
// Static device scratch
// ---------------------------------------------------------------------------
__device__ __align__(16) float          g_M  [(size_t)ET * FD];  // fp32 (sim)
__device__ __align__(16) float          g_A2 [(size_t)ET * FD];  // fp32 (sim)
__device__ __align__(16) __nv_bfloat16  g_Mh [(size_t)ET * FD];
__device__ __align__(16) __nv_bfloat16  g_Ml [(size_t)ET * FD];
__device__ __align__(16) __nv_bfloat16  g_Y1h[(size_t)ET * HD];
__device__ __align__(16) __nv_bfloat16  g_Y1l[(size_t)ET * HD];
__device__ __align__(16) __nv_bfloat16  g_Y2h[(size_t)ET * HD];
__device__ __align__(16) __nv_bfloat16  g_Y2l[(size_t)ET * HD];
__device__ __align__(16) __nv_bfloat16  g_W1h[(size_t)HD * FD];
__device__ __align__(16) __nv_bfloat16  g_W1l[(size_t)HD * FD];
__device__ __align__(16) __nv_bfloat16  g_W2h[(size_t)HD * HD];
__device__ __align__(16) __nv_bfloat16  g_W2l[(size_t)HD * HD];
__device__ __align__(16) __nv_bfloat16  g_W3h[(size_t)FD * HD];
__device__ __align__(16) __nv_bfloat16  g_W3l[(size_t)FD * HD];

// ---------------------------------------------------------------------------
// PTX helpers (plain sm_103-legal: mma.sync / cp.async only)
// ---------------------------------------------------------------------------
__device__ __forceinline__ uint32_t smem_u32(const void* p) {
    uint32_t a;
    asm("{ .reg .u64 t; cvta.to.shared.u64 t, %1; cvt.u32.u64 %0, t; }"
        : "=r"(a) : "l"(p));
    return a;
}
__device__ __forceinline__ void cp_async16(uint32_t dst, const void* src) {
    asm volatile("cp.async.cg.shared.global [%0], [%1], 16;"
                 :: "r"(dst), "l"(src) : "memory");
}
__device__ __forceinline__ void cp_commit() {
    asm volatile("cp.async.commit_group;" ::: "memory");
}
template <int N>
__device__ __forceinline__ void cp_wait() {
    asm volatile("cp.async.wait_group %0;" :: "n"(N) : "memory");
}
__device__ __forceinline__ void mma16816(float* c, const uint32_t* a,
                                         const uint32_t* b) {
    asm volatile(
        "mma.sync.aligned.m16n8k16.row.col.f32.bf16.bf16.f32 "
        "{%0,%1,%2,%3}, {%4,%5,%6,%7}, {%8,%9}, {%0,%1,%2,%3};"
        : "+f"(c[0]), "+f"(c[1]), "+f"(c[2]), "+f"(c[3])
        : "r"(a[0]), "r"(a[1]), "r"(a[2]), "r"(a[3]), "r"(b[0]), "r"(b[1]));
}

// ---------------------------------------------------------------------------
// Kernel 1: per-episode class means -> g_M (fp32) + split bf16 (g_Mh/g_Ml)
// ---------------------------------------------------------------------------
__global__ void __launch_bounds__(256) mean_kernel(const float* __restrict__ nf) {
    int b  = blockIdx.x;
    int f4 = threadIdx.x;                       // 0..255
    const float4* src = (const float4*)nf + (size_t)b * NN * (FD / 4);
    float4*        dst = (float4*)g_M    + (size_t)b * E6 * (FD / 4);
    __nv_bfloat16* dh  = g_Mh + (size_t)b * E6 * FD;
    __nv_bfloat16* dl  = g_Ml + (size_t)b * E6 * FD;

    auto split4 = [&](size_t base, float4 o) {
        float v[4] = {o.x, o.y, o.z, o.w};
#pragma unroll
        for (int k = 0; k < 4; k++) {
            __nv_bfloat16 h = __float2bfloat16(v[k]);
            dh[base + k] = h;
            dl[base + k] = __float2bfloat16(v[k] - __bfloat162float(h));
        }
    };

#pragma unroll
    for (int c = 0; c < 5; c++) {
        float4 s0 = src[(c * 5 + 0) * (FD / 4) + f4];
        float4 s1 = src[(c * 5 + 1) * (FD / 4) + f4];
        float4 s2 = src[(c * 5 + 2) * (FD / 4) + f4];
        float4 s3 = src[(c * 5 + 3) * (FD / 4) + f4];
        float4 s4 = src[(c * 5 + 4) * (FD / 4) + f4];
        float4 o;
        o.x = (s0.x + s1.x + s2.x + s3.x + s4.x) / 5.0f;
        o.y = (s0.y + s1.y + s2.y + s3.y + s4.y) / 5.0f;
        o.z = (s0.z + s1.z + s2.z + s3.z + s4.z) / 5.0f;
        o.w = (s0.w + s1.w + s2.w + s3.w + s4.w) / 5.0f;
        dst[c * (FD / 4) + f4] = o;
        split4((size_t)c * FD + f4 * 4, o);
    }
    float4 q = src[25 * (FD / 4) + f4];
    dst[5 * (FD / 4) + f4] = q;
    split4((size_t)5 * FD + f4 * 4, q);
}

// ---------------------------------------------------------------------------
// Weight split: fp32 -> (hi, lo) bf16
// ---------------------------------------------------------------------------
__global__ void __launch_bounds__(256) split_kernel(const float* __restrict__ w,
                                                    __nv_bfloat16* __restrict__ hi,
                                                    __nv_bfloat16* __restrict__ lo,
                                                    int n) {
    int i = blockIdx.x * blockDim.x + threadIdx.x;
    if (i < n) {
        float x = w[i];
        __nv_bfloat16 h = __float2bfloat16(x);
        hi[i] = h;
        lo[i] = __float2bfloat16(x - __bfloat162float(h));
    }
}

// ---------------------------------------------------------------------------
// 3-term split-bf16 HMMA GEMM with PRE-SPLIT operands (no converts in loop):
//   C = A * W^T,  acc += Ah*Wh + Al*Wh + Ah*Wl   (fp32 accumulate)
// Tile 128x128, 256 threads (8 warps 2x4), warp tile 64x32 (m16n8k16).
// Four bf16 tiles per chunk (Ah, Al, Wh, Wl), 128 rows x 32 k, row pad 80B,
// double-buffered cp.async. Fragments via manual LDS.32 (PTX-table mapping,
// proven in R8/R9): reg = 4B at row*80 + ks*32 + tg*4 (+16 for k+8).
// LAYER 1/2: bias+BN+leaky -> split bf16 Y.   LAYER 3: sigmoid^2 -> fp32 A2.
// ---------------------------------------------------------------------------
#define RPADB 80                       // bytes per smem row
#define TILEB (128 * RPADB)            // 10240 bytes per tile
#define BUFB  (4 * TILEB)              // Ah, Al, Wh, Wl
#define GEMM_SMEM_BYTES (2 * BUFB)     // 81920

template <int K, int NCOL, int LAYER>
__global__ void __launch_bounds__(256, 2) gemm_ps(
    const __nv_bfloat16* __restrict__ Ah,
    const __nv_bfloat16* __restrict__ Al,
    const __nv_bfloat16* __restrict__ Wh,
    const __nv_bfloat16* __restrict__ Wl,
    const float* __restrict__ bias,
    const float* __restrict__ gamma,
    const float* __restrict__ beta,
    const float* __restrict__ rmean,
    const float* __restrict__ rvar)
{
    extern __shared__ __align__(16) unsigned char sbuf[];

    constexpr int NCHUNK = K / 32;

    const int tid  = threadIdx.x;
    const int wid  = tid >> 5;
    const int lane = tid & 31;
    const int wrow = wid >> 2;           // 0..1
    const int wcol = wid & 3;            // 0..3
    const int g    = lane >> 2;          // 0..7
    const int tg   = lane & 3;           // 0..3
    const int row0 = blockIdx.x * 128;
    const int col0 = blockIdx.y * 128;

    const __nv_bfloat16* srcs[4] = {Ah, Al, Wh, Wl};

    auto issue_chunk = [&](int kb, int buf) {
        const uint32_t base = smem_u32(sbuf) + (uint32_t)buf * BUFB;
#pragma unroll
        for (int i = 0; i < 8; i++) {
            const int tile = i >> 1;                 // 0..3
            const int rem  = (i & 1) * 256 + tid;    // 0..511
            const int r    = rem >> 2;               // 0..127
            const int s    = rem & 3;                // 16B seg (8 bf16)
            const int rb   = (tile < 2) ? row0 : col0;
            cp_async16(base + tile * TILEB + r * RPADB + s * 16,
                       srcs[tile] + (size_t)(rb + r) * K + kb + s * 8);
        }
        cp_commit();
    };

    float acc[4][4][4];
#pragma unroll
    for (int mt = 0; mt < 4; mt++)
#pragma unroll
        for (int nt = 0; nt < 4; nt++)
#pragma unroll
            for (int e = 0; e < 4; e++) acc[mt][nt][e] = 0.0f;

    issue_chunk(0, 0);

    for (int cc = 0; cc < NCHUNK; cc++) {
        const int buf = cc & 1;
        if (cc + 1 < NCHUNK) { issue_chunk((cc + 1) * 32, buf ^ 1); cp_wait<1>(); }
        else                 { cp_wait<0>(); }
        __syncthreads();

        const unsigned char* pAh = sbuf + (size_t)buf * BUFB;
        const unsigned char* pAl = pAh + TILEB;
        const unsigned char* pWh = pAl + TILEB;
        const unsigned char* pWl = pWh + TILEB;

#pragma unroll
        for (int ks = 0; ks < 2; ks++) {
            const int koff = ks * 32 + tg * 4;
            // ---- B fragments: hi and lo, 4 n-tiles ----
            uint32_t bh[4][2], bl[4][2];
#pragma unroll
            for (int nt = 0; nt < 4; nt++) {
                const int ro = (wcol * 32 + nt * 8 + g) * RPADB + koff;
                bh[nt][0] = *(const uint32_t*)(pWh + ro);
                bh[nt][1] = *(const uint32_t*)(pWh + ro + 16);
                bl[nt][0] = *(const uint32_t*)(pWl + ro);
                bl[nt][1] = *(const uint32_t*)(pWl + ro + 16);
            }
            // ---- A fragments per m-tile, 3 MMA terms ----
#pragma unroll
            for (int mt = 0; mt < 4; mt++) {
                const int ro = (wrow * 64 + mt * 16 + g) * RPADB + koff;
                uint32_t ah[4], al[4];
                ah[0] = *(const uint32_t*)(pAh + ro);
                ah[1] = *(const uint32_t*)(pAh + ro + 8 * RPADB);
                ah[2] = *(const uint32_t*)(pAh + ro + 16);
                ah[3] = *(const uint32_t*)(pAh + ro + 8 * RPADB + 16);
                al[0] = *(const uint32_t*)(pAl + ro);
                al[1] = *(const uint32_t*)(pAl + ro + 8 * RPADB);
                al[2] = *(const uint32_t*)(pAl + ro + 16);
                al[3] = *(const uint32_t*)(pAl + ro + 8 * RPADB + 16);
#pragma unroll
                for (int nt = 0; nt < 4; nt++) {
                    mma16816(acc[mt][nt], ah, bh[nt]);
                    mma16816(acc[mt][nt], al, bh[nt]);
                    mma16816(acc[mt][nt], ah, bl[nt]);
                }
            }
        }
        __syncthreads();   // WAR guard before re-issuing into this buffer
    }

    // -------- fused epilogue --------
    const int er0 = row0 + wrow * 64 + g;
    const int ec0 = col0 + wcol * 32 + 2 * tg;

#pragma unroll
    for (int nt = 0; nt < 4; nt++) {
        const int h0 = ec0 + nt * 8;
        float sc0, sh0 = 0.f, sc1, sh1 = 0.f;
        if (LAYER == 3) {
            sc0 = bias[h0]; sc1 = bias[h0 + 1];
        } else {
            float s0 = gamma[h0] * rsqrtf(rvar[h0] + 1e-5f);
            float s1 = gamma[h0 + 1] * rsqrtf(rvar[h0 + 1] + 1e-5f);
            sc0 = s0; sh0 = (bias[h0] - rmean[h0]) * s0 + beta[h0];
            sc1 = s1; sh1 = (bias[h0 + 1] - rmean[h0 + 1]) * s1 + beta[h0 + 1];
        }
#pragma unroll
        for (int mt = 0; mt < 4; mt++) {
#pragma unroll
            for (int half = 0; half < 2; half++) {
                int r = er0 + mt * 16 + half * 8;
                float v0 = acc[mt][nt][half * 2 + 0];
                float v1 = acc[mt][nt][half * 2 + 1];
                if (LAYER == 3) {
                    float y0 = v0 + sc0, y1 = v1 + sc1;
                    float q0 = 1.0f / (1.0f + expf(-y0));
                    float q1 = 1.0f / (1.0f + expf(-y1));
                    float2 o; o.x = q0 * q0; o.y = q1 * q1;
                    *(float2*)(g_A2 + (size_t)r * NCOL + h0) = o;
                } else {
                    float y0 = v0 * sc0 + sh0;
                    float y1 = v1 * sc1 + sh1;
                    y0 = (y0 > 0.0f) ? y0 : 0.01f * y0;
                    y1 = (y1 > 0.0f) ? y1 : 0.01f * y1;
                    __nv_bfloat16* Ch = (LAYER == 1) ? g_Y1h : g_Y2h;
                    __nv_bfloat16* Cl = (LAYER == 1) ? g_Y1l : g_Y2l;
                    __nv_bfloat16 h0b = __float2bfloat16(y0);
                    __nv_bfloat16 h1b = __float2bfloat16(y1);
                    __nv_bfloat162 hp; hp.x = h0b; hp.y = h1b;
                    __nv_bfloat162 lp;
                    lp.x = __float2bfloat16(y0 - __bfloat162float(h0b));
                    lp.y = __float2bfloat16(y1 - __bfloat162float(h1b));
                    *(__nv_bfloat162*)(Ch + (size_t)r * NCOL + h0) = hp;
                    *(__nv_bfloat162*)(Cl + (size_t)r * NCOL + h0) = lp;
                }
            }
        }
    }
}

// ---------------------------------------------------------------------------
// Kernel: per-episode 6x6 cosine similarity + broadcast (proven)
// ---------------------------------------------------------------------------
__global__ void __launch_bounds__(128) sim_kernel(float* __restrict__ out) {
    const int b    = blockIdx.x;
    const int tid  = threadIdx.x;
    const int wid  = tid >> 5;
    const int lane = tid & 31;

    __shared__ float sM[E6][512];
    __shared__ float sA[E6][512];
    __shared__ float s_sim[36];

    const float* Mb = g_M  + (size_t)b * E6 * FD;
    const float* Ab = g_A2 + (size_t)b * E6 * FD;

    float d[9], nij[9], nji[9];
#pragma unroll
    for (int q = 0; q < 9; q++) { d[q] = 0.0f; nij[q] = 0.0f; nji[q] = 0.0f; }

    for (int half = 0; half < 2; half++) {
        __syncthreads();
        for (int idx = tid; idx < E6 * 512; idx += 128) {
            int row = idx >> 9;
            int col = idx & 511;
            sM[row][col] = Mb[row * FD + half * 512 + col];
            sA[row][col] = Ab[row * FD + half * 512 + col];
        }
        __syncthreads();

        int q = 0;
        for (int p = wid; p < 36; p += 4, q++) {
            int i = p / 6, j = p % 6;
            float dd = 0.0f, ni = 0.0f, nj = 0.0f;
            for (int f = lane; f < 512; f += 32) {
                float ai = sA[i][f], aj = sA[j][f];
                float xi = sM[i][f], xj = sM[j][f];
                float pi = ai * xi;
                float pj = aj * xj;
                dd += pi * pj;
                ni += pi * xi * aj;
                nj += pj * xj * ai;
            }
            d[q] += dd; nij[q] += ni; nji[q] += nj;
        }
    }

    {
        int q = 0;
        for (int p = wid; p < 36; p += 4, q++) {
            float dd = d[q], ni = nij[q], nj = nji[q];
#pragma unroll
            for (int off = 16; off > 0; off >>= 1) {
                dd += __shfl_xor_sync(0xffffffffu, dd, off);
                ni += __shfl_xor_sync(0xffffffffu, ni, off);
                nj += __shfl_xor_sync(0xffffffffu, nj, off);
            }
            if (lane == 0)
                s_sim[p] = dd / (sqrtf(ni) * sqrtf(nj));
        }
    }
    __syncthreads();

    size_t base = (size_t)b * (2 * NN * NN);
    for (int idx = tid; idx < 2 * NN * NN; idx += 128) {
        int s = idx / (NN * NN);
        int rr = idx - s * (NN * NN);
        int i = rr / NN;
        int j = rr - i * NN;
        int ci = (i < 25) ? (i / 5) : 5;
        int cj = (j < 25) ? (j / 5) : 5;
        float v = s_sim[ci * 6 + cj];
        if (s) v = 1.0f - v;
        out[base + idx] = fminf(fmaxf(v, 0.0f), 1.0f);
    }
}

// ---------------------------------------------------------------------------
// Launch (graph-capturable)
// ---------------------------------------------------------------------------
extern "C" void kernel_launch(void* const* d_in, const int* in_sizes, int n_in,
                              void* d_out, int out_size) {
    const float* nf  = (const float*)d_in[0];
    const float* w1  = (const float*)d_in[1];
    const float* b1  = (const float*)d_in[2];
    const float* g1  = (const float*)d_in[3];
    const float* be1 = (const float*)d_in[4];
    const float* m1  = (const float*)d_in[5];
    const float* v1  = (const float*)d_in[6];
    const float* w2  = (const float*)d_in[7];
    const float* b2  = (const float*)d_in[8];
    const float* g2  = (const float*)d_in[9];
    const float* be2 = (const float*)d_in[10];
    const float* m2  = (const float*)d_in[11];
    const float* v2  = (const float*)d_in[12];
    const float* w3  = (const float*)d_in[13];
    const float* b3  = (const float*)d_in[14];
    float* out = (float*)d_out;

    __nv_bfloat16 *pMh, *pMl, *pY1h, *pY1l, *pY2h, *pY2l;
    __nv_bfloat16 *pW1h, *pW1l, *pW2h, *pW2l, *pW3h, *pW3l;
    cudaGetSymbolAddress((void**)&pMh,  g_Mh);
    cudaGetSymbolAddress((void**)&pMl,  g_Ml);
    cudaGetSymbolAddress((void**)&pY1h, g_Y1h);
    cudaGetSymbolAddress((void**)&pY1l, g_Y1l);
    cudaGetSymbolAddress((void**)&pY2h, g_Y2h);
    cudaGetSymbolAddress((void**)&pY2l, g_Y2l);
    cudaGetSymbolAddress((void**)&pW1h, g_W1h);
    cudaGetSymbolAddress((void**)&pW1l, g_W1l);
    cudaGetSymbolAddress((void**)&pW2h, g_W2h);
    cudaGetSymbolAddress((void**)&pW2l, g_W2l);
    cudaGetSymbolAddress((void**)&pW3h, g_W3h);
    cudaGetSymbolAddress((void**)&pW3l, g_W3l);

    cudaFuncSetAttribute(gemm_ps<FD, HD, 1>,
                         cudaFuncAttributeMaxDynamicSharedMemorySize,
                         GEMM_SMEM_BYTES);
    cudaFuncSetAttribute(gemm_ps<HD, HD, 2>,
                         cudaFuncAttributeMaxDynamicSharedMemorySize,
                         GEMM_SMEM_BYTES);
    cudaFuncSetAttribute(gemm_ps<HD, FD, 3>,
                         cudaFuncAttributeMaxDynamicSharedMemorySize,
                         GEMM_SMEM_BYTES);

    // weight splits (fp32 -> hi/lo bf16)
    split_kernel<<<(HD * FD + 255) / 256, 256>>>(w1, pW1h, pW1l, HD * FD);
    split_kernel<<<(HD * HD + 255) / 256, 256>>>(w2, pW2h, pW2l, HD * HD);
    split_kernel<<<(FD * HD + 255) / 256, 256>>>(w3, pW3h, pW3l, FD * HD);

    // class means (fp32 + split bf16)
    mean_kernel<<<NB, 256>>>(nf);

    // Y1 = leaky(bn1(M @ w1^T + b1))
    gemm_ps<FD, HD, 1><<<dim3(ET / 128, HD / 128), 256, GEMM_SMEM_BYTES>>>(
        pMh, pMl, pW1h, pW1l, b1, g1, be1, m1, v1);
    // Y2 = leaky(bn2(Y1 @ w2^T + b2))
    gemm_ps<HD, HD, 2><<<dim3(ET / 128, HD / 128), 256, GEMM_SMEM_BYTES>>>(
        pY1h, pY1l, pW2h, pW2l, b2, g2, be2, m2, v2);
    // A2 = sigmoid(Y2 @ w3^T + b3)^2
    gemm_ps<HD, FD, 3><<<dim3(ET / 128, FD / 128), 256, GEMM_SMEM_BYTES>>>(
        pY2h, pY2l, pW3h, pW3l, b3, nullptr, nullptr, nullptr, nullptr);

    // per-episode 6x6 cosine sim -> broadcast [2,26,26]
    sim_kernel<<<NB, 128>>>(out);
}

// round 13
// speedup vs baseline: 2.3925x; 1.0800x over previous
#include <cuda_runtime.h>
#include <cuda_bf16.h>
#include <math.h>
#include <cstdint>

// Problem constants
#define NB     2048            // batch (episodes)
#define NN     26              // nodes per episode
#define FD     1024            // feature dim
#define HD     512             // hidden dim
#define E6     6               // distinct rows per episode (5 class means + query)
#define ET     (NB * E6)       // 12288 effective GEMM rows

// ---------------------------------------------------------------------------
// Static device scratch.  All bf16 hi/lo arrays use a k-interleaved layout:
// within each 16-element k-group, position 4j..4j+3 holds k = {2j,2j+1,2j+8,2j+9}.
// This makes one LDS.64 deliver both fragment registers of an mma operand.
// ---------------------------------------------------------------------------
__device__ __align__(16) float          g_M  [(size_t)ET * FD];  // fp32 (sim)
__device__ __align__(16) float          g_A2 [(size_t)ET * FD];  // fp32 (sim)
__device__ __align__(16) __nv_bfloat16  g_Mh [(size_t)ET * FD];
__device__ __align__(16) __nv_bfloat16  g_Ml [(size_t)ET * FD];
__device__ __align__(16) __nv_bfloat16  g_Y1h[(size_t)ET * HD];
__device__ __align__(16) __nv_bfloat16  g_Y1l[(size_t)ET * HD];
__device__ __align__(16) __nv_bfloat16  g_Y2h[(size_t)ET * HD];
__device__ __align__(16) __nv_bfloat16  g_Y2l[(size_t)ET * HD];
__device__ __align__(16) __nv_bfloat16  g_W1h[(size_t)HD * FD];
__device__ __align__(16) __nv_bfloat16  g_W1l[(size_t)HD * FD];
__device__ __align__(16) __nv_bfloat16  g_W2h[(size_t)HD * HD];
__device__ __align__(16) __nv_bfloat16  g_W2l[(size_t)HD * HD];
__device__ __align__(16) __nv_bfloat16  g_W3h[(size_t)FD * HD];
__device__ __align__(16) __nv_bfloat16  g_W3l[(size_t)FD * HD];

// permuted position of k (within its 16-group)
__device__ __forceinline__ int pperm(int km) {
    return (km < 8) ? ((km >> 1) * 4 + (km & 1))
                    : (((km - 8) >> 1) * 4 + 2 + (km & 1));
}

// ---------------------------------------------------------------------------
// PTX helpers (plain sm_103-legal: mma.sync / cp.async only)
// ---------------------------------------------------------------------------
__device__ __forceinline__ uint32_t smem_u32(const void* p) {
    uint32_t a;
    asm("{ .reg .u64 t; cvta.to.shared.u64 t, %1; cvt.u32.u64 %0, t; }"
        : "=r"(a) : "l"(p));
    return a;
}
__device__ __forceinline__ void cp_async16(uint32_t dst, const void* src) {
    asm volatile("cp.async.cg.shared.global [%0], [%1], 16;"
                 :: "r"(dst), "l"(src) : "memory");
}
__device__ __forceinline__ void cp_commit() {
    asm volatile("cp.async.commit_group;" ::: "memory");
}
template <int N>
__device__ __forceinline__ void cp_wait() {
    asm volatile("cp.async.wait_group %0;" :: "n"(N) : "memory");
}
__device__ __forceinline__ void mma16816(float* c, const uint32_t* a,
                                         const uint32_t* b) {
    asm volatile(
        "mma.sync.aligned.m16n8k16.row.col.f32.bf16.bf16.f32 "
        "{%0,%1,%2,%3}, {%4,%5,%6,%7}, {%8,%9}, {%0,%1,%2,%3};"
        : "+f"(c[0]), "+f"(c[1]), "+f"(c[2]), "+f"(c[3])
        : "r"(a[0]), "r"(a[1]), "r"(a[2]), "r"(a[3]), "r"(b[0]), "r"(b[1]));
}

// ---------------------------------------------------------------------------
// Kernel 1: per-episode class means -> g_M (fp32) + permuted split bf16
// ---------------------------------------------------------------------------
__global__ void __launch_bounds__(256) mean_kernel(const float* __restrict__ nf) {
    int b  = blockIdx.x;
    int f4 = threadIdx.x;                       // 0..255
    const float4* src = (const float4*)nf + (size_t)b * NN * (FD / 4);
    float4*        dst = (float4*)g_M    + (size_t)b * E6 * (FD / 4);
    __nv_bfloat16* dh  = g_Mh + (size_t)b * E6 * FD;
    __nv_bfloat16* dl  = g_Ml + (size_t)b * E6 * FD;

    const int k0   = f4 * 4;
    const int grp  = k0 & ~15;
    const int p01  = grp + pperm(k0 & 15);        // pos of (k0, k0+1)
    const int p23  = grp + pperm((k0 & 15) + 2);  // pos of (k0+2, k0+3)

    auto split4 = [&](size_t rowbase, float4 o) {
        __nv_bfloat162 h01, h23, l01, l23;
        h01.x = __float2bfloat16(o.x); h01.y = __float2bfloat16(o.y);
        h23.x = __float2bfloat16(o.z); h23.y = __float2bfloat16(o.w);
        l01.x = __float2bfloat16(o.x - __bfloat162float(h01.x));
        l01.y = __float2bfloat16(o.y - __bfloat162float(h01.y));
        l23.x = __float2bfloat16(o.z - __bfloat162float(h23.x));
        l23.y = __float2bfloat16(o.w - __bfloat162float(h23.y));
        *(__nv_bfloat162*)(dh + rowbase + p01) = h01;
        *(__nv_bfloat162*)(dh + rowbase + p23) = h23;
        *(__nv_bfloat162*)(dl + rowbase + p01) = l01;
        *(__nv_bfloat162*)(dl + rowbase + p23) = l23;
    };

#pragma unroll
    for (int c = 0; c < 5; c++) {
        float4 s0 = src[(c * 5 + 0) * (FD / 4) + f4];
        float4 s1 = src[(c * 5 + 1) * (FD / 4) + f4];
        float4 s2 = src[(c * 5 + 2) * (FD / 4) + f4];
        float4 s3 = src[(c * 5 + 3) * (FD / 4) + f4];
        float4 s4 = src[(c * 5 + 4) * (FD / 4) + f4];
        float4 o;
        o.x = (s0.x + s1.x + s2.x + s3.x + s4.x) / 5.0f;
        o.y = (s0.y + s1.y + s2.y + s3.y + s4.y) / 5.0f;
        o.z = (s0.z + s1.z + s2.z + s3.z + s4.z) / 5.0f;
        o.w = (s0.w + s1.w + s2.w + s3.w + s4.w) / 5.0f;
        dst[c * (FD / 4) + f4] = o;
        split4((size_t)c * FD, o);
    }
    float4 q = src[25 * (FD / 4) + f4];
    dst[5 * (FD / 4) + f4] = q;
    split4((size_t)5 * FD, q);
}

// ---------------------------------------------------------------------------
// Weight split: fp32 -> (hi, lo) bf16, permuted k layout
// ---------------------------------------------------------------------------
__global__ void __launch_bounds__(256) split_kernel(const float* __restrict__ w,
                                                    __nv_bfloat16* __restrict__ hi,
                                                    __nv_bfloat16* __restrict__ lo,
                                                    int n, int K) {
    int i = blockIdx.x * blockDim.x + threadIdx.x;
    if (i < n) {
        int k   = i % K;
        int row = i / K;
        int pi  = row * K + (k & ~15) + pperm(k & 15);
        float x = w[i];
        __nv_bfloat16 h = __float2bfloat16(x);
        hi[pi] = h;
        lo[pi] = __float2bfloat16(x - __bfloat162float(h));
    }
}

// ---------------------------------------------------------------------------
// 3-term split-bf16 HMMA GEMM, pre-split permuted operands, LDS.64 fragments:
//   acc += Ah*Wh + Al*Wh + Ah*Wl   (fp32 accumulate)
// Tile 128x128, 256 threads (8 warps 2x4), warp tile 64x32 (m16n8k16).
// Four bf16 tiles per chunk (Ah, Al, Wh, Wl): 128 rows x 64B data in 96B rows
// (pad proven conflict-free for LDS.64).  Double-buffered, 1 sync per chunk.
// LAYER 1/2: bias+BN+leaky -> split bf16 (permuted).  LAYER 3: sigmoid^2 fp32.
// ---------------------------------------------------------------------------
#define RPADB 96                       // bytes per smem row (64 data + 32 pad)
#define TILEB (128 * RPADB)            // 12288 bytes per tile
#define BUFB  (4 * TILEB)              // Ah, Al, Wh, Wl
#define GEMM_SMEM_BYTES (2 * BUFB)     // 98304

template <int K, int NCOL, int LAYER>
__global__ void __launch_bounds__(256, 2) gemm_ps(
    const __nv_bfloat16* __restrict__ Ah,
    const __nv_bfloat16* __restrict__ Al,
    const __nv_bfloat16* __restrict__ Wh,
    const __nv_bfloat16* __restrict__ Wl,
    const float* __restrict__ bias,
    const float* __restrict__ gamma,
    const float* __restrict__ beta,
    const float* __restrict__ rmean,
    const float* __restrict__ rvar)
{
    extern __shared__ __align__(16) unsigned char sbuf[];

    constexpr int NCHUNK = K / 32;

    const int tid  = threadIdx.x;
    const int wid  = tid >> 5;
    const int lane = tid & 31;
    const int wrow = wid >> 2;           // 0..1
    const int wcol = wid & 3;            // 0..3
    const int g    = lane >> 2;          // 0..7
    const int tg   = lane & 3;           // 0..3
    const int row0 = blockIdx.x * 128;
    const int col0 = blockIdx.y * 128;

    const __nv_bfloat16* srcs[4] = {Ah, Al, Wh, Wl};

    auto issue_chunk = [&](int kb, int buf) {
        const uint32_t base = smem_u32(sbuf) + (uint32_t)buf * BUFB;
#pragma unroll
        for (int i = 0; i < 8; i++) {
            const int tile = i >> 1;                 // 0..3
            const int rem  = (i & 1) * 256 + tid;    // 0..511
            const int r    = rem >> 2;               // 0..127
            const int s    = rem & 3;                // 16B seg (8 bf16)
            const int rb   = (tile < 2) ? row0 : col0;
            cp_async16(base + tile * TILEB + r * RPADB + s * 16,
                       srcs[tile] + (size_t)(rb + r) * K + kb + s * 8);
        }
        cp_commit();
    };

    float acc[4][4][4];
#pragma unroll
    for (int mt = 0; mt < 4; mt++)
#pragma unroll
        for (int nt = 0; nt < 4; nt++)
#pragma unroll
            for (int e = 0; e < 4; e++) acc[mt][nt][e] = 0.0f;

    issue_chunk(0, 0);

    for (int cc = 0; cc < NCHUNK; cc++) {
        const int buf = cc & 1;
        cp_wait<0>();          // only this chunk's group is outstanding
        __syncthreads();       // data visible + prev compute of buf^1 done
        if (cc + 1 < NCHUNK) issue_chunk((cc + 1) * 32, buf ^ 1);

        const unsigned char* pAh = sbuf + (size_t)buf * BUFB;
        const unsigned char* pAl = pAh + TILEB;
        const unsigned char* pWh = pAl + TILEB;
        const unsigned char* pWl = pWh + TILEB;

#pragma unroll
        for (int ks = 0; ks < 2; ks++) {
            const int koff = ks * 32 + tg * 8;
            // ---- B fragments: one LDS.64 each for hi and lo, 4 n-tiles ----
            uint32_t bh[4][2], bl[4][2];
#pragma unroll
            for (int nt = 0; nt < 4; nt++) {
                const int ro = (wcol * 32 + nt * 8 + g) * RPADB + koff;
                uint2 vh = *(const uint2*)(pWh + ro);
                uint2 vl = *(const uint2*)(pWl + ro);
                bh[nt][0] = vh.x; bh[nt][1] = vh.y;
                bl[nt][0] = vl.x; bl[nt][1] = vl.y;
            }
            // ---- A fragments per m-tile (2 LDS.64 hi + 2 lo), 3 MMA terms --
#pragma unroll
            for (int mt = 0; mt < 4; mt++) {
                const int ro = (wrow * 64 + mt * 16 + g) * RPADB + koff;
                uint2 h1 = *(const uint2*)(pAh + ro);             // row g
                uint2 h2 = *(const uint2*)(pAh + ro + 8 * RPADB); // row g+8
                uint2 l1 = *(const uint2*)(pAl + ro);
                uint2 l2 = *(const uint2*)(pAl + ro + 8 * RPADB);
                uint32_t ah[4] = {h1.x, h2.x, h1.y, h2.y};
                uint32_t al[4] = {l1.x, l2.x, l1.y, l2.y};
#pragma unroll
                for (int nt = 0; nt < 4; nt++) {
                    mma16816(acc[mt][nt], ah, bh[nt]);
                    mma16816(acc[mt][nt], al, bh[nt]);
                    mma16816(acc[mt][nt], ah, bl[nt]);
                }
            }
        }
    }

    // -------- fused epilogue --------
    const int er0 = row0 + wrow * 64 + g;
    const int ec0 = col0 + wcol * 32 + 2 * tg;

#pragma unroll
    for (int nt = 0; nt < 4; nt++) {
        const int h0 = ec0 + nt * 8;
        float sc0, sh0 = 0.f, sc1, sh1 = 0.f;
        if (LAYER == 3) {
            sc0 = bias[h0]; sc1 = bias[h0 + 1];
        } else {
            float s0 = gamma[h0] * rsqrtf(rvar[h0] + 1e-5f);
            float s1 = gamma[h0 + 1] * rsqrtf(rvar[h0 + 1] + 1e-5f);
            sc0 = s0; sh0 = (bias[h0] - rmean[h0]) * s0 + beta[h0];
            sc1 = s1; sh1 = (bias[h0 + 1] - rmean[h0 + 1]) * s1 + beta[h0 + 1];
        }
        const int hperm = (h0 & ~15) + pperm(h0 & 15);   // permuted pair pos
#pragma unroll
        for (int mt = 0; mt < 4; mt++) {
#pragma unroll
            for (int half = 0; half < 2; half++) {
                int r = er0 + mt * 16 + half * 8;
                float v0 = acc[mt][nt][half * 2 + 0];
                float v1 = acc[mt][nt][half * 2 + 1];
                if (LAYER == 3) {
                    float y0 = v0 + sc0, y1 = v1 + sc1;
                    float q0 = 1.0f / (1.0f + expf(-y0));
                    float q1 = 1.0f / (1.0f + expf(-y1));
                    float2 o; o.x = q0 * q0; o.y = q1 * q1;
                    *(float2*)(g_A2 + (size_t)r * NCOL + h0) = o;
                } else {
                    float y0 = v0 * sc0 + sh0;
                    float y1 = v1 * sc1 + sh1;
                    y0 = (y0 > 0.0f) ? y0 : 0.01f * y0;
                    y1 = (y1 > 0.0f) ? y1 : 0.01f * y1;
                    __nv_bfloat16* Ch = (LAYER == 1) ? g_Y1h : g_Y2h;
                    __nv_bfloat16* Cl = (LAYER == 1) ? g_Y1l : g_Y2l;
                    __nv_bfloat162 hp, lp;
                    hp.x = __float2bfloat16(y0);
                    hp.y = __float2bfloat16(y1);
                    lp.x = __float2bfloat16(y0 - __bfloat162float(hp.x));
                    lp.y = __float2bfloat16(y1 - __bfloat162float(hp.y));
                    *(__nv_bfloat162*)(Ch + (size_t)r * NCOL + hperm) = hp;
                    *(__nv_bfloat162*)(Cl + (size_t)r * NCOL + hperm) = lp;
                }
            }
        }
    }
}

// ---------------------------------------------------------------------------
// Kernel: per-episode 6x6 cosine similarity, ONE WARP PER EPISODE.
// Register-resident: 21 symmetric dots + 36 n2 accumulators; 12 coalesced
// LDG per f-iter; butterfly reduce; 57 scalars through smem.
// FIX vs R12: the 36-pair sim loop now strides lanes (t = lane; t < 36;
// t += 32) — the old `if (lane < 36)` left pairs 32..35 uncomputed (a warp
// has 32 lanes), which was the R0/R12 6.5e-2 error.
// ---------------------------------------------------------------------------
__global__ void __launch_bounds__(256) sim_kernel(float* __restrict__ out) {
    const int tid  = threadIdx.x;
    const int wid  = tid >> 5;
    const int lane = tid & 31;
    const int ep   = blockIdx.x * 8 + wid;      // episode

    __shared__ float sred[8][57];
    __shared__ float ssim[8][36];

    const float* Mb = g_M  + (size_t)ep * E6 * FD;
    const float* Ab = g_A2 + (size_t)ep * E6 * FD;

    float d[21], n2[36];
#pragma unroll
    for (int t = 0; t < 21; t++) d[t] = 0.0f;
#pragma unroll
    for (int t = 0; t < 36; t++) n2[t] = 0.0f;

    for (int it = 0; it < FD / 32; it++) {
        const int f = lane + it * 32;
        float x[6], a[6];
#pragma unroll
        for (int i = 0; i < 6; i++) {
            x[i] = Mb[i * FD + f];
            a[i] = Ab[i * FD + f];
        }
        float p[6], q[6];
#pragma unroll
        for (int i = 0; i < 6; i++) {
            p[i] = a[i] * x[i];
            q[i] = p[i] * x[i];
        }
        {
            int t = 0;
#pragma unroll
            for (int i = 0; i < 6; i++)
#pragma unroll
                for (int j = i; j < 6; j++) { d[t] += p[i] * p[j]; t++; }
        }
#pragma unroll
        for (int i = 0; i < 6; i++)
#pragma unroll
            for (int j = 0; j < 6; j++)
                n2[i * 6 + j] += q[i] * a[j];
    }

    // warp butterfly reduce (all lanes end with the full sums)
#pragma unroll
    for (int off = 16; off > 0; off >>= 1) {
#pragma unroll
        for (int t = 0; t < 21; t++)
            d[t] += __shfl_xor_sync(0xffffffffu, d[t], off);
#pragma unroll
        for (int t = 0; t < 36; t++)
            n2[t] += __shfl_xor_sync(0xffffffffu, n2[t], off);
    }

    // scatter to smem with static register indexing
#pragma unroll
    for (int t = 0; t < 21; t++)
        if (lane == t) sred[wid][t] = d[t];
#pragma unroll
    for (int t = 0; t < 32; t++)
        if (lane == t) sred[wid][21 + t] = n2[t];
#pragma unroll
    for (int t = 32; t < 36; t++)
        if (lane == t - 32 + 8) sred[wid][21 + t] = n2[t];   // lanes 8..11
    __syncwarp();

    // all 36 ordered pairs (lanes 0..3 handle two pairs) — FIXED
    for (int t = lane; t < 36; t += 32) {
        int i = t / 6, j = t % 6;
        int lo = i < j ? i : j;
        int hi = i < j ? j : i;
        int tidx = 6 * lo - (lo * (lo - 1)) / 2 + (hi - lo);
        float dd  = sred[wid][tidx];
        float nij = sred[wid][21 + i * 6 + j];
        float nji = sred[wid][21 + j * 6 + i];
        ssim[wid][t] = dd / (sqrtf(nij) * sqrtf(nji));
    }
    __syncwarp();

    size_t base = (size_t)ep * (2 * NN * NN);
    for (int idx = lane; idx < 2 * NN * NN; idx += 32) {
        int s  = idx / (NN * NN);
        int rr = idx - s * (NN * NN);
        int i  = rr / NN;
        int j  = rr - i * NN;
        int ci = (i < 25) ? (i / 5) : 5;
        int cj = (j < 25) ? (j / 5) : 5;
        float v = ssim[wid][ci * 6 + cj];
        if (s) v = 1.0f - v;
        out[base + idx] = fminf(fmaxf(v, 0.0f), 1.0f);
    }
}

// ---------------------------------------------------------------------------
// Launch (graph-capturable)
// ---------------------------------------------------------------------------
extern "C" void kernel_launch(void* const* d_in, const int* in_sizes, int n_in,
                              void* d_out, int out_size) {
    const float* nf  = (const float*)d_in[0];
    const float* w1  = (const float*)d_in[1];
    const float* b1  = (const float*)d_in[2];
    const float* g1  = (const float*)d_in[3];
    const float* be1 = (const float*)d_in[4];
    const float* m1  = (const float*)d_in[5];
    const float* v1  = (const float*)d_in[6];
    const float* w2  = (const float*)d_in[7];
    const float* b2  = (const float*)d_in[8];
    const float* g2  = (const float*)d_in[9];
    const float* be2 = (const float*)d_in[10];
    const float* m2  = (const float*)d_in[11];
    const float* v2  = (const float*)d_in[12];
    const float* w3  = (const float*)d_in[13];
    const float* b3  = (const float*)d_in[14];
    float* out = (float*)d_out;

    __nv_bfloat16 *pMh, *pMl, *pY1h, *pY1l, *pY2h, *pY2l;
    __nv_bfloat16 *pW1h, *pW1l, *pW2h, *pW2l, *pW3h, *pW3l;
    cudaGetSymbolAddress((void**)&pMh,  g_Mh);
    cudaGetSymbolAddress((void**)&pMl,  g_Ml);
    cudaGetSymbolAddress((void**)&pY1h, g_Y1h);
    cudaGetSymbolAddress((void**)&pY1l, g_Y1l);
    cudaGetSymbolAddress((void**)&pY2h, g_Y2h);
    cudaGetSymbolAddress((void**)&pY2l, g_Y2l);
    cudaGetSymbolAddress((void**)&pW1h, g_W1h);
    cudaGetSymbolAddress((void**)&pW1l, g_W1l);
    cudaGetSymbolAddress((void**)&pW2h, g_W2h);
    cudaGetSymbolAddress((void**)&pW2l, g_W2l);
    cudaGetSymbolAddress((void**)&pW3h, g_W3h);
    cudaGetSymbolAddress((void**)&pW3l, g_W3l);

    cudaFuncSetAttribute(gemm_ps<FD, HD, 1>,
                         cudaFuncAttributeMaxDynamicSharedMemorySize,
                         GEMM_SMEM_BYTES);
    cudaFuncSetAttribute(gemm_ps<HD, HD, 2>,
                         cudaFuncAttributeMaxDynamicSharedMemorySize,
                         GEMM_SMEM_BYTES);
    cudaFuncSetAttribute(gemm_ps<HD, FD, 3>,
                         cudaFuncAttributeMaxDynamicSharedMemorySize,
                         GEMM_SMEM_BYTES);

    // weight splits (fp32 -> hi/lo bf16, permuted layout)
    split_kernel<<<(HD * FD + 255) / 256, 256>>>(w1, pW1h, pW1l, HD * FD, FD);
    split_kernel<<<(HD * HD + 255) / 256, 256>>>(w2, pW2h, pW2l, HD * HD, HD);
    split_kernel<<<(FD * HD + 255) / 256, 256>>>(w3, pW3h, pW3l, FD * HD, HD);

    // class means (fp32 + permuted split bf16)
    mean_kernel<<<NB, 256>>>(nf);

    // Y1 = leaky(bn1(M @ w1^T + b1))
    gemm_ps<FD, HD, 1><<<dim3(ET / 128, HD / 128), 256, GEMM_SMEM_BYTES>>>(
        pMh, pMl, pW1h, pW1l, b1, g1, be1, m1, v1);
    // Y2 = leaky(bn2(Y1 @ w2^T + b2))
    gemm_ps<HD, HD, 2><<<dim3(ET / 128, HD / 128), 256, GEMM_SMEM_BYTES>>>(
        pY1h, pY1l, pW2h, pW2l, b2, g2, be2, m2, v2);
    // A2 = sigmoid(Y2 @ w3^T + b3)^2
    gemm_ps<HD, FD, 3><<<dim3(ET / 128, HD / 128 * 2), 256, GEMM_SMEM_BYTES>>>(
        pY2h, pY2l, pW3h, pW3l, b3, nullptr, nullptr, nullptr, nullptr);

    // per-episode 6x6 cosine sim -> broadcast [2,26,26]  (one warp/episode)
    sim_kernel<<<NB / 8, 256>>>(out);
}

// round 14
// speedup vs baseline: 2.4957x; 1.0431x over previous
#include <cuda_runtime.h>
#include <cuda_bf16.h>
#include <math.h>
#include <cstdint>

// Problem constants
#define NB     2048            // batch (episodes)
#define NN     26              // nodes per episode
#define FD     1024            // feature dim
#define HD     512             // hidden dim
#define E6     6               // distinct rows per episode (5 class means + query)
#define ET     (NB * E6)       // 12288 effective GEMM rows

// ---------------------------------------------------------------------------
// Static device scratch.  All bf16 hi/lo arrays use a k-interleaved layout:
// within each 16-element k-group, position 4j..4j+3 holds k = {2j,2j+1,2j+8,2j+9}.
// One LDS.64 then delivers both fragment registers of an mma operand.
// ---------------------------------------------------------------------------
__device__ __align__(16) float          g_M  [(size_t)ET * FD];  // fp32 (sim)
__device__ __align__(16) float          g_A2 [(size_t)ET * FD];  // fp32 (sim)
__device__ __align__(16) __nv_bfloat16  g_Mh [(size_t)ET * FD];
__device__ __align__(16) __nv_bfloat16  g_Ml [(size_t)ET * FD];
__device__ __align__(16) __nv_bfloat16  g_Y1h[(size_t)ET * HD];
__device__ __align__(16) __nv_bfloat16  g_Y1l[(size_t)ET * HD];
__device__ __align__(16) __nv_bfloat16  g_Y2h[(size_t)ET * HD];
__device__ __align__(16) __nv_bfloat16  g_Y2l[(size_t)ET * HD];
__device__ __align__(16) __nv_bfloat16  g_W1h[(size_t)HD * FD];
__device__ __align__(16) __nv_bfloat16  g_W1l[(size_t)HD * FD];
__device__ __align__(16) __nv_bfloat16  g_W2h[(size_t)HD * HD];
__device__ __align__(16) __nv_bfloat16  g_W2l[(size_t)HD * HD];
__device__ __align__(16) __nv_bfloat16  g_W3h[(size_t)FD * HD];
__device__ __align__(16) __nv_bfloat16  g_W3l[(size_t)FD * HD];

// permuted position of k (within its 16-group)
__device__ __forceinline__ int pperm(int km) {
    return (km < 8) ? ((km >> 1) * 4 + (km & 1))
                    : (((km - 8) >> 1) * 4 + 2 + (km & 1));
}

// ---------------------------------------------------------------------------
// PTX helpers (plain sm_103-legal: mma.sync / cp.async only)
// ---------------------------------------------------------------------------
__device__ __forceinline__ uint32_t smem_u32(const void* p) {
    uint32_t a;
    asm("{ .reg .u64 t; cvta.to.shared.u64 t, %1; cvt.u32.u64 %0, t; }"
        : "=r"(a) : "l"(p));
    return a;
}
__device__ __forceinline__ void cp_async16(uint32_t dst, const void* src) {
    asm volatile("cp.async.cg.shared.global [%0], [%1], 16;"
                 :: "r"(dst), "l"(src) : "memory");
}
__device__ __forceinline__ void cp_commit() {
    asm volatile("cp.async.commit_group;" ::: "memory");
}
template <int N>
__device__ __forceinline__ void cp_wait() {
    asm volatile("cp.async.wait_group %0;" :: "n"(N) : "memory");
}
__device__ __forceinline__ void mma16816(float* c, const uint32_t* a,
                                         const uint32_t* b) {
    asm volatile(
        "mma.sync.aligned.m16n8k16.row.col.f32.bf16.bf16.f32 "
        "{%0,%1,%2,%3}, {%4,%5,%6,%7}, {%8,%9}, {%0,%1,%2,%3};"
        : "+f"(c[0]), "+f"(c[1]), "+f"(c[2]), "+f"(c[3])
        : "r"(a[0]), "r"(a[1]), "r"(a[2]), "r"(a[3]), "r"(b[0]), "r"(b[1]));
}

// ---------------------------------------------------------------------------
// Kernel 1: per-episode class means -> g_M (fp32) + permuted split bf16
// ---------------------------------------------------------------------------
__global__ void __launch_bounds__(256) mean_kernel(const float* __restrict__ nf) {
    int b  = blockIdx.x;
    int f4 = threadIdx.x;                       // 0..255
    const float4* src = (const float4*)nf + (size_t)b * NN * (FD / 4);
    float4*        dst = (float4*)g_M    + (size_t)b * E6 * (FD / 4);
    __nv_bfloat16* dh  = g_Mh + (size_t)b * E6 * FD;
    __nv_bfloat16* dl  = g_Ml + (size_t)b * E6 * FD;

    const int k0   = f4 * 4;
    const int grp  = k0 & ~15;
    const int p01  = grp + pperm(k0 & 15);        // pos of (k0, k0+1)
    const int p23  = grp + pperm((k0 & 15) + 2);  // pos of (k0+2, k0+3)

    auto split4 = [&](size_t rowbase, float4 o) {
        __nv_bfloat162 h01, h23, l01, l23;
        h01.x = __float2bfloat16(o.x); h01.y = __float2bfloat16(o.y);
        h23.x = __float2bfloat16(o.z); h23.y = __float2bfloat16(o.w);
        l01.x = __float2bfloat16(o.x - __bfloat162float(h01.x));
        l01.y = __float2bfloat16(o.y - __bfloat162float(h01.y));
        l23.x = __float2bfloat16(o.z - __bfloat162float(h23.x));
        l23.y = __float2bfloat16(o.w - __bfloat162float(h23.y));
        *(__nv_bfloat162*)(dh + rowbase + p01) = h01;
        *(__nv_bfloat162*)(dh + rowbase + p23) = h23;
        *(__nv_bfloat162*)(dl + rowbase + p01) = l01;
        *(__nv_bfloat162*)(dl + rowbase + p23) = l23;
    };

#pragma unroll
    for (int c = 0; c < 5; c++) {
        float4 s0 = src[(c * 5 + 0) * (FD / 4) + f4];
        float4 s1 = src[(c * 5 + 1) * (FD / 4) + f4];
        float4 s2 = src[(c * 5 + 2) * (FD / 4) + f4];
        float4 s3 = src[(c * 5 + 3) * (FD / 4) + f4];
        float4 s4 = src[(c * 5 + 4) * (FD / 4) + f4];
        float4 o;
        o.x = (s0.x + s1.x + s2.x + s3.x + s4.x) / 5.0f;
        o.y = (s0.y + s1.y + s2.y + s3.y + s4.y) / 5.0f;
        o.z = (s0.z + s1.z + s2.z + s3.z + s4.z) / 5.0f;
        o.w = (s0.w + s1.w + s2.w + s3.w + s4.w) / 5.0f;
        dst[c * (FD / 4) + f4] = o;
        split4((size_t)c * FD, o);
    }
    float4 q = src[25 * (FD / 4) + f4];
    dst[5 * (FD / 4) + f4] = q;
    split4((size_t)5 * FD, q);
}

// ---------------------------------------------------------------------------
// Weight split: fp32 -> (hi, lo) bf16, permuted k layout
// ---------------------------------------------------------------------------
__global__ void __launch_bounds__(256) split_kernel(const float* __restrict__ w,
                                                    __nv_bfloat16* __restrict__ hi,
                                                    __nv_bfloat16* __restrict__ lo,
                                                    int n, int K) {
    int i = blockIdx.x * blockDim.x + threadIdx.x;
    if (i < n) {
        int k   = i % K;
        int row = i / K;
        int pi  = row * K + (k & ~15) + pperm(k & 15);
        float x = w[i];
        __nv_bfloat16 h = __float2bfloat16(x);
        hi[pi] = h;
        lo[pi] = __float2bfloat16(x - __bfloat162float(h));
    }
}

// ---------------------------------------------------------------------------
// 3-term split-bf16 HMMA GEMM, pre-split permuted operands, LDS.64 fragments:
//   acc += Ah*Wh + Al*Wh + Ah*Wl   (fp32 accumulate)
// Tile 128x128, 128 threads = 4 warps (2x2), WARP TILE 64x64 (m16n8k16,
// mt=4 x nt=8): halves smem traffic per MMA vs the 64x32 warp tile.
// Four bf16 tiles per chunk (Ah, Al, Wh, Wl): 128 rows x 64B data in 96B rows
// (pad proven conflict-free for LDS.64).  Double-buffered, 1 sync per chunk.
// LAYER 1/2: bias+BN+leaky -> split bf16 (permuted).  LAYER 3: sigmoid^2 fp32.
// ---------------------------------------------------------------------------
#define RPADB 96                       // bytes per smem row (64 data + 32 pad)
#define TILEB (128 * RPADB)            // 12288 bytes per tile
#define BUFB  (4 * TILEB)              // Ah, Al, Wh, Wl
#define GEMM_SMEM_BYTES (2 * BUFB)     // 98304

template <int K, int NCOL, int LAYER>
__global__ void __launch_bounds__(128, 2) gemm_ps(
    const __nv_bfloat16* __restrict__ Ah,
    const __nv_bfloat16* __restrict__ Al,
    const __nv_bfloat16* __restrict__ Wh,
    const __nv_bfloat16* __restrict__ Wl,
    const float* __restrict__ bias,
    const float* __restrict__ gamma,
    const float* __restrict__ beta,
    const float* __restrict__ rmean,
    const float* __restrict__ rvar)
{
    extern __shared__ __align__(16) unsigned char sbuf[];

    constexpr int NCHUNK = K / 32;

    const int tid  = threadIdx.x;
    const int wid  = tid >> 5;
    const int lane = tid & 31;
    const int wrow = wid >> 1;           // 0..1 -> 64-row block
    const int wcol = wid & 1;            // 0..1 -> 64-col block
    const int g    = lane >> 2;          // 0..7
    const int tg   = lane & 3;           // 0..3
    const int row0 = blockIdx.x * 128;
    const int col0 = blockIdx.y * 128;

    const __nv_bfloat16* srcs[4] = {Ah, Al, Wh, Wl};

    auto issue_chunk = [&](int kb, int buf) {
        const uint32_t base = smem_u32(sbuf) + (uint32_t)buf * BUFB;
#pragma unroll
        for (int i = 0; i < 16; i++) {
            const int idx  = i * 128 + tid;          // 0..2047
            const int tile = idx >> 9;               // 0..3
            const int rem  = idx & 511;
            const int r    = rem >> 2;               // 0..127
            const int s    = rem & 3;                // 16B seg (8 bf16)
            const int rb   = (tile < 2) ? row0 : col0;
            cp_async16(base + tile * TILEB + r * RPADB + s * 16,
                       srcs[tile] + (size_t)(rb + r) * K + kb + s * 8);
        }
        cp_commit();
    };

    float acc[4][8][4];
#pragma unroll
    for (int mt = 0; mt < 4; mt++)
#pragma unroll
        for (int nt = 0; nt < 8; nt++)
#pragma unroll
            for (int e = 0; e < 4; e++) acc[mt][nt][e] = 0.0f;

    issue_chunk(0, 0);

    for (int cc = 0; cc < NCHUNK; cc++) {
        const int buf = cc & 1;
        cp_wait<0>();          // only this chunk's group is outstanding
        __syncthreads();       // data visible + prev compute of buf^1 done
        if (cc + 1 < NCHUNK) issue_chunk((cc + 1) * 32, buf ^ 1);

        const unsigned char* pAh = sbuf + (size_t)buf * BUFB;
        const unsigned char* pAl = pAh + TILEB;
        const unsigned char* pWh = pAl + TILEB;
        const unsigned char* pWl = pWh + TILEB;

#pragma unroll
        for (int ks = 0; ks < 2; ks++) {
            const int koff = ks * 32 + tg * 8;
            // ---- B fragments: one LDS.64 each for hi and lo, 8 n-tiles ----
            uint32_t bh[8][2], bl[8][2];
#pragma unroll
            for (int nt = 0; nt < 8; nt++) {
                const int ro = (wcol * 64 + nt * 8 + g) * RPADB + koff;
                uint2 vh = *(const uint2*)(pWh + ro);
                uint2 vl = *(const uint2*)(pWl + ro);
                bh[nt][0] = vh.x; bh[nt][1] = vh.y;
                bl[nt][0] = vl.x; bl[nt][1] = vl.y;
            }
            // ---- A fragments per m-tile (2 LDS.64 hi + 2 lo), 3 MMA terms --
#pragma unroll
            for (int mt = 0; mt < 4; mt++) {
                const int ro = (wrow * 64 + mt * 16 + g) * RPADB + koff;
                uint2 h1 = *(const uint2*)(pAh + ro);             // row g
                uint2 h2 = *(const uint2*)(pAh + ro + 8 * RPADB); // row g+8
                uint2 l1 = *(const uint2*)(pAl + ro);
                uint2 l2 = *(const uint2*)(pAl + ro + 8 * RPADB);
                uint32_t ah[4] = {h1.x, h2.x, h1.y, h2.y};
                uint32_t al[4] = {l1.x, l2.x, l1.y, l2.y};
#pragma unroll
                for (int nt = 0; nt < 8; nt++) {
                    mma16816(acc[mt][nt], ah, bh[nt]);
                    mma16816(acc[mt][nt], al, bh[nt]);
                    mma16816(acc[mt][nt], ah, bl[nt]);
                }
            }
        }
    }

    // -------- fused epilogue --------
    const int er0 = row0 + wrow * 64 + g;
    const int ec0 = col0 + wcol * 64 + 2 * tg;

#pragma unroll
    for (int nt = 0; nt < 8; nt++) {
        const int h0 = ec0 + nt * 8;
        float sc0, sh0 = 0.f, sc1, sh1 = 0.f;
        if (LAYER == 3) {
            sc0 = bias[h0]; sc1 = bias[h0 + 1];
        } else {
            float s0 = gamma[h0] * rsqrtf(rvar[h0] + 1e-5f);
            float s1 = gamma[h0 + 1] * rsqrtf(rvar[h0 + 1] + 1e-5f);
            sc0 = s0; sh0 = (bias[h0] - rmean[h0]) * s0 + beta[h0];
            sc1 = s1; sh1 = (bias[h0 + 1] - rmean[h0 + 1]) * s1 + beta[h0 + 1];
        }
        const int hperm = (h0 & ~15) + pperm(h0 & 15);   // permuted pair pos
#pragma unroll
        for (int mt = 0; mt < 4; mt++) {
#pragma unroll
            for (int half = 0; half < 2; half++) {
                int r = er0 + mt * 16 + half * 8;
                float v0 = acc[mt][nt][half * 2 + 0];
                float v1 = acc[mt][nt][half * 2 + 1];
                if (LAYER == 3) {
                    float y0 = v0 + sc0, y1 = v1 + sc1;
                    float q0 = 1.0f / (1.0f + expf(-y0));
                    float q1 = 1.0f / (1.0f + expf(-y1));
                    float2 o; o.x = q0 * q0; o.y = q1 * q1;
                    *(float2*)(g_A2 + (size_t)r * NCOL + h0) = o;
                } else {
                    float y0 = v0 * sc0 + sh0;
                    float y1 = v1 * sc1 + sh1;
                    y0 = (y0 > 0.0f) ? y0 : 0.01f * y0;
                    y1 = (y1 > 0.0f) ? y1 : 0.01f * y1;
                    __nv_bfloat16* Ch = (LAYER == 1) ? g_Y1h : g_Y2h;
                    __nv_bfloat16* Cl = (LAYER == 1) ? g_Y1l : g_Y2l;
                    __nv_bfloat162 hp, lp;
                    hp.x = __float2bfloat16(y0);
                    hp.y = __float2bfloat16(y1);
                    lp.x = __float2bfloat16(y0 - __bfloat162float(hp.x));
                    lp.y = __float2bfloat16(y1 - __bfloat162float(hp.y));
                    *(__nv_bfloat162*)(Ch + (size_t)r * NCOL + hperm) = hp;
                    *(__nv_bfloat162*)(Cl + (size_t)r * NCOL + hperm) = lp;
                }
            }
        }
    }
}

// ---------------------------------------------------------------------------
// Kernel: per-episode 6x6 cosine similarity, ONE WARP PER EPISODE (proven).
// ---------------------------------------------------------------------------
__global__ void __launch_bounds__(256) sim_kernel(float* __restrict__ out) {
    const int tid  = threadIdx.x;
    const int wid  = tid >> 5;
    const int lane = tid & 31;
    const int ep   = blockIdx.x * 8 + wid;      // episode

    __shared__ float sred[8][57];
    __shared__ float ssim[8][36];

    const float* Mb = g_M  + (size_t)ep * E6 * FD;
    const float* Ab = g_A2 + (size_t)ep * E6 * FD;

    float d[21], n2[36];
#pragma unroll
    for (int t = 0; t < 21; t++) d[t] = 0.0f;
#pragma unroll
    for (int t = 0; t < 36; t++) n2[t] = 0.0f;

    for (int it = 0; it < FD / 32; it++) {
        const int f = lane + it * 32;
        float x[6], a[6];
#pragma unroll
        for (int i = 0; i < 6; i++) {
            x[i] = Mb[i * FD + f];
            a[i] = Ab[i * FD + f];
        }
        float p[6], q[6];
#pragma unroll
        for (int i = 0; i < 6; i++) {
            p[i] = a[i] * x[i];
            q[i] = p[i] * x[i];
        }
        {
            int t = 0;
#pragma unroll
            for (int i = 0; i < 6; i++)
#pragma unroll
                for (int j = i; j < 6; j++) { d[t] += p[i] * p[j]; t++; }
        }
#pragma unroll
        for (int i = 0; i < 6; i++)
#pragma unroll
            for (int j = 0; j < 6; j++)
                n2[i * 6 + j] += q[i] * a[j];
    }

    // warp butterfly reduce (all lanes end with the full sums)
#pragma unroll
    for (int off = 16; off > 0; off >>= 1) {
#pragma unroll
        for (int t = 0; t < 21; t++)
            d[t] += __shfl_xor_sync(0xffffffffu, d[t], off);
#pragma unroll
        for (int t = 0; t < 36; t++)
            n2[t] += __shfl_xor_sync(0xffffffffu, n2[t], off);
    }

    // scatter to smem with static register indexing
#pragma unroll
    for (int t = 0; t < 21; t++)
        if (lane == t) sred[wid][t] = d[t];
#pragma unroll
    for (int t = 0; t < 32; t++)
        if (lane == t) sred[wid][21 + t] = n2[t];
#pragma unroll
    for (int t = 32; t < 36; t++)
        if (lane == t - 32 + 8) sred[wid][21 + t] = n2[t];   // lanes 8..11
    __syncwarp();

    // all 36 ordered pairs (lanes 0..3 handle two pairs)
    for (int t = lane; t < 36; t += 32) {
        int i = t / 6, j = t % 6;
        int lo = i < j ? i : j;
        int hi = i < j ? j : i;
        int tidx = 6 * lo - (lo * (lo - 1)) / 2 + (hi - lo);
        float dd  = sred[wid][tidx];
        float nij = sred[wid][21 + i * 6 + j];
        float nji = sred[wid][21 + j * 6 + i];
        ssim[wid][t] = dd / (sqrtf(nij) * sqrtf(nji));
    }
    __syncwarp();

    size_t base = (size_t)ep * (2 * NN * NN);
    for (int idx = lane; idx < 2 * NN * NN; idx += 32) {
        int s  = idx / (NN * NN);
        int rr = idx - s * (NN * NN);
        int i  = rr / NN;
        int j  = rr - i * NN;
        int ci = (i < 25) ? (i / 5) : 5;
        int cj = (j < 25) ? (j / 5) : 5;
        float v = ssim[wid][ci * 6 + cj];
        if (s) v = 1.0f - v;
        out[base + idx] = fminf(fmaxf(v, 0.0f), 1.0f);
    }
}

// ---------------------------------------------------------------------------
// Launch (graph-capturable)
// ---------------------------------------------------------------------------
extern "C" void kernel_launch(void* const* d_in, const int* in_sizes, int n_in,
                              void* d_out, int out_size) {
    const float* nf  = (const float*)d_in[0];
    const float* w1  = (const float*)d_in[1];
    const float* b1  = (const float*)d_in[2];
    const float* g1  = (const float*)d_in[3];
    const float* be1 = (const float*)d_in[4];
    const float* m1  = (const float*)d_in[5];
    const float* v1  = (const float*)d_in[6];
    const float* w2  = (const float*)d_in[7];
    const float* b2  = (const float*)d_in[8];
    const float* g2  = (const float*)d_in[9];
    const float* be2 = (const float*)d_in[10];
    const float* m2  = (const float*)d_in[11];
    const float* v2  = (const float*)d_in[12];
    const float* w3  = (const float*)d_in[13];
    const float* b3  = (const float*)d_in[14];
    float* out = (float*)d_out;

    __nv_bfloat16 *pMh, *pMl, *pY1h, *pY1l, *pY2h, *pY2l;
    __nv_bfloat16 *pW1h, *pW1l, *pW2h, *pW2l, *pW3h, *pW3l;
    cudaGetSymbolAddress((void**)&pMh,  g_Mh);
    cudaGetSymbolAddress((void**)&pMl,  g_Ml);
    cudaGetSymbolAddress((void**)&pY1h, g_Y1h);
    cudaGetSymbolAddress((void**)&pY1l, g_Y1l);
    cudaGetSymbolAddress((void**)&pY2h, g_Y2h);
    cudaGetSymbolAddress((void**)&pY2l, g_Y2l);
    cudaGetSymbolAddress((void**)&pW1h, g_W1h);
    cudaGetSymbolAddress((void**)&pW1l, g_W1l);
    cudaGetSymbolAddress((void**)&pW2h, g_W2h);
    cudaGetSymbolAddress((void**)&pW2l, g_W2l);
    cudaGetSymbolAddress((void**)&pW3h, g_W3h);
    cudaGetSymbolAddress((void**)&pW3l, g_W3l);

    cudaFuncSetAttribute(gemm_ps<FD, HD, 1>,
                         cudaFuncAttributeMaxDynamicSharedMemorySize,
                         GEMM_SMEM_BYTES);
    cudaFuncSetAttribute(gemm_ps<HD, HD, 2>,
                         cudaFuncAttributeMaxDynamicSharedMemorySize,
                         GEMM_SMEM_BYTES);
    cudaFuncSetAttribute(gemm_ps<HD, FD, 3>,
                         cudaFuncAttributeMaxDynamicSharedMemorySize,
                         GEMM_SMEM_BYTES);

    // weight splits (fp32 -> hi/lo bf16, permuted layout)
    split_kernel<<<(HD * FD + 255) / 256, 256>>>(w1, pW1h, pW1l, HD * FD, FD);
    split_kernel<<<(HD * HD + 255) / 256, 256>>>(w2, pW2h, pW2l, HD * HD, HD);
    split_kernel<<<(FD * HD + 255) / 256, 256>>>(w3, pW3h, pW3l, FD * HD, HD);

    // class means (fp32 + permuted split bf16)
    mean_kernel<<<NB, 256>>>(nf);

    // Y1 = leaky(bn1(M @ w1^T + b1))
    gemm_ps<FD, HD, 1><<<dim3(ET / 128, HD / 128), 128, GEMM_SMEM_BYTES>>>(
        pMh, pMl, pW1h, pW1l, b1, g1, be1, m1, v1);
    // Y2 = leaky(bn2(Y1 @ w2^T + b2))
    gemm_ps<HD, HD, 2><<<dim3(ET / 128, HD / 128), 128, GEMM_SMEM_BYTES>>>(
        pY1h, pY1l, pW2h, pW2l, b2, g2, be2, m2, v2);
    // A2 = sigmoid(Y2 @ w3^T + b3)^2
    gemm_ps<HD, FD, 3><<<dim3(ET / 128, FD / 128), 128, GEMM_SMEM_BYTES>>>(
        pY2h, pY2l, pW3h, pW3l, b3, nullptr, nullptr, nullptr, nullptr);

    // per-episode 6x6 cosine sim -> broadcast [2,26,26]  (one warp/episode)
    sim_kernel<<<NB / 8, 256>>>(out);
}